// round 1
// baseline (speedup 1.0000x reference)
#include <cuda_runtime.h>
#include <math.h>

#define B_  4
#define T_  4096
#define NE_ 2048
#define HD_ 128

// Scratch for Q,K,V projections: 3 x 8MB. __device__ globals (no allocation).
__device__ float g_Q[B_ * T_ * HD_];
__device__ float g_K[B_ * T_ * HD_];
__device__ float g_V[B_ * T_ * HD_];

// ---------------------------------------------------------------------------
// Kernel 1: fused QKV projection. C[M=16384, N=128] = x[M, 2048] @ W[2048, 128]
// blockIdx.y in {0,1,2} selects (Wq->g_Q, Wk->g_K, Wv->g_V).
// BM=64, BN=128, BK=16. 256 threads, each computes a 4x8 register tile.
// ---------------------------------------------------------------------------
__global__ __launch_bounds__(256) void qkv_gemm_kernel(
    const float* __restrict__ x, const float* __restrict__ Wq,
    const float* __restrict__ Wk, const float* __restrict__ Wv)
{
    __shared__ float As[64][17];   // +1 pad
    __shared__ float Bs[16][128];

    const float* W;
    float* O;
    if (blockIdx.y == 0)      { W = Wq; O = g_Q; }
    else if (blockIdx.y == 1) { W = Wk; O = g_K; }
    else                      { W = Wv; O = g_V; }

    const int m0  = blockIdx.x * 64;
    const int tid = threadIdx.x;
    const int tx  = tid & 15;        // 0..15 -> N
    const int ty  = tid >> 4;        // 0..15 -> M

    float acc[4][8];
#pragma unroll
    for (int r = 0; r < 4; r++)
#pragma unroll
        for (int c = 0; c < 8; c++) acc[r][c] = 0.f;

    const int ar = tid >> 2;          // 0..63
    const int ac = (tid & 3) << 2;    // 0,4,8,12

    for (int k0 = 0; k0 < NE_; k0 += 16) {
        // A tile: 64x16, one float4 per thread
        float4 av = *(const float4*)(x + (size_t)(m0 + ar) * NE_ + k0 + ac);
        As[ar][ac + 0] = av.x; As[ar][ac + 1] = av.y;
        As[ar][ac + 2] = av.z; As[ar][ac + 3] = av.w;
        // B tile: 16x128, two float4 per thread
#pragma unroll
        for (int q = 0; q < 2; q++) {
            int idx = tid + q * 256;
            int r = idx >> 5, c = (idx & 31) << 2;
            *(float4*)&Bs[r][c] = *(const float4*)(W + (size_t)(k0 + r) * HD_ + c);
        }
        __syncthreads();

#pragma unroll
        for (int kk = 0; kk < 16; kk++) {
            float a[4];
#pragma unroll
            for (int r = 0; r < 4; r++) a[r] = As[ty * 4 + r][kk];
            float4 b0 = *(float4*)&Bs[kk][tx * 8];
            float4 b1 = *(float4*)&Bs[kk][tx * 8 + 4];
            float bb[8] = {b0.x, b0.y, b0.z, b0.w, b1.x, b1.y, b1.z, b1.w};
#pragma unroll
            for (int r = 0; r < 4; r++)
#pragma unroll
                for (int c = 0; c < 8; c++)
                    acc[r][c] = fmaf(a[r], bb[c], acc[r][c]);
        }
        __syncthreads();
    }

#pragma unroll
    for (int r = 0; r < 4; r++) {
        size_t base = (size_t)(m0 + ty * 4 + r) * HD_ + tx * 8;
        float4 o0 = make_float4(acc[r][0], acc[r][1], acc[r][2], acc[r][3]);
        float4 o1 = make_float4(acc[r][4], acc[r][5], acc[r][6], acc[r][7]);
        *(float4*)(O + base)     = o0;
        *(float4*)(O + base + 4) = o1;
    }
}

// ---------------------------------------------------------------------------
// Kernel 2: causal flash attention, fp32.
// Block = 256 threads (16x16). BQ = BK = 64, D = 128.
// Thread (ty,tx): S tile entries rows ty*4+0..3, cols tx*4+0..3.
//                 O accum     rows ty*4+0..3, dims tx*8+0..7.
// Row-wide reductions via 16-lane shuffles (one ty per 16-lane group).
// ---------------------------------------------------------------------------
#define BQ 64
#define BKV 64
#define QS_STRIDE 132   // float4-aligned, broadcast reads
#define KS_STRIDE 129   // scalar reads, 2-way conflicts only
#define VS_STRIDE 132   // float4-aligned, phase-friendly reads
#define PS_STRIDE 65

#define ATTN_SMEM_FLOATS (BQ*QS_STRIDE + BKV*KS_STRIDE + BKV*VS_STRIDE + BQ*PS_STRIDE)
#define ATTN_SMEM_BYTES  (ATTN_SMEM_FLOATS * 4)

__global__ __launch_bounds__(256, 1) void attn_kernel(float* __restrict__ out)
{
    extern __shared__ float sm[];
    float* Qs = sm;
    float* Ks = Qs + BQ * QS_STRIDE;
    float* Vs = Ks + BKV * KS_STRIDE;
    float* Ps = Vs + BKV * VS_STRIDE;

    const int b   = blockIdx.y;
    const int qt  = (int)gridDim.x - 1 - (int)blockIdx.x;  // heavy tiles first
    const int q0  = qt * BQ;
    const int tid = threadIdx.x;
    const int tx  = tid & 15;
    const int ty  = tid >> 4;
    const float scale = 0.08838834764831845f;  // 1/sqrt(128)

    const float* Qg = g_Q + (size_t)b * T_ * HD_;
    const float* Kg = g_K + (size_t)b * T_ * HD_;
    const float* Vg = g_V + (size_t)b * T_ * HD_;

    // Load Q tile (pre-scaled)
    for (int t = tid; t < BQ * 32; t += 256) {
        int r = t >> 5, c4 = (t & 31) << 2;
        float4 v = *(const float4*)(Qg + (size_t)(q0 + r) * HD_ + c4);
        v.x *= scale; v.y *= scale; v.z *= scale; v.w *= scale;
        *(float4*)&Qs[r * QS_STRIDE + c4] = v;
    }

    float m_i[4], l_i[4], acc[4][8];
#pragma unroll
    for (int r = 0; r < 4; r++) {
        m_i[r] = -INFINITY; l_i[r] = 0.f;
#pragma unroll
        for (int c = 0; c < 8; c++) acc[r][c] = 0.f;
    }

    const int nkv = qt + 1;
    for (int kt = 0; kt < nkv; kt++) {
        const int k0 = kt * BKV;
        // Load K (scalar store, stride 129) and V (vector store, stride 132)
        for (int t = tid; t < BKV * 32; t += 256) {
            int r = t >> 5, c4 = (t & 31) << 2;
            float4 kv = *(const float4*)(Kg + (size_t)(k0 + r) * HD_ + c4);
            Ks[r * KS_STRIDE + c4 + 0] = kv.x;
            Ks[r * KS_STRIDE + c4 + 1] = kv.y;
            Ks[r * KS_STRIDE + c4 + 2] = kv.z;
            Ks[r * KS_STRIDE + c4 + 3] = kv.w;
            float4 vv = *(const float4*)(Vg + (size_t)(k0 + r) * HD_ + c4);
            *(float4*)&Vs[r * VS_STRIDE + c4] = vv;
        }
        __syncthreads();

        // ---- S = Q @ K^T (4x4 per thread) ----
        float s[4][4];
#pragma unroll
        for (int r = 0; r < 4; r++)
#pragma unroll
            for (int c = 0; c < 4; c++) s[r][c] = 0.f;

#pragma unroll 2
        for (int d = 0; d < HD_; d += 4) {
            float qv[4][4];
#pragma unroll
            for (int r = 0; r < 4; r++) {
                float4 q4 = *(const float4*)&Qs[(ty * 4 + r) * QS_STRIDE + d];
                qv[r][0] = q4.x; qv[r][1] = q4.y; qv[r][2] = q4.z; qv[r][3] = q4.w;
            }
#pragma unroll
            for (int dd = 0; dd < 4; dd++) {
                float kv[4];
#pragma unroll
                for (int c = 0; c < 4; c++)
                    kv[c] = Ks[(tx * 4 + c) * KS_STRIDE + d + dd];
#pragma unroll
                for (int r = 0; r < 4; r++)
#pragma unroll
                    for (int c = 0; c < 4; c++)
                        s[r][c] = fmaf(qv[r][dd], kv[c], s[r][c]);
            }
        }

        // Causal mask (only the diagonal tile needs it)
        if (kt == qt) {
#pragma unroll
            for (int r = 0; r < 4; r++)
#pragma unroll
                for (int c = 0; c < 4; c++)
                    if ((k0 + tx * 4 + c) > (q0 + ty * 4 + r)) s[r][c] = -INFINITY;
        }

        // ---- online softmax ----
        float mnew[4], alpha[4];
#pragma unroll
        for (int r = 0; r < 4; r++) {
            float mx = fmaxf(fmaxf(s[r][0], s[r][1]), fmaxf(s[r][2], s[r][3]));
#pragma unroll
            for (int off = 8; off; off >>= 1)
                mx = fmaxf(mx, __shfl_xor_sync(0xffffffffu, mx, off));
            mnew[r]  = fmaxf(m_i[r], mx);
            alpha[r] = __expf(m_i[r] - mnew[r]);  // exp(-inf - finite) = 0
        }
#pragma unroll
        for (int r = 0; r < 4; r++) {
            float sum = 0.f;
#pragma unroll
            for (int c = 0; c < 4; c++) {
                float p = __expf(s[r][c] - mnew[r]);
                Ps[(ty * 4 + r) * PS_STRIDE + tx * 4 + c] = p;
                sum += p;
            }
#pragma unroll
            for (int off = 8; off; off >>= 1)
                sum += __shfl_xor_sync(0xffffffffu, sum, off);
            l_i[r] = l_i[r] * alpha[r] + sum;
            m_i[r] = mnew[r];
#pragma unroll
            for (int c = 0; c < 8; c++) acc[r][c] *= alpha[r];
        }
        __syncthreads();   // Ps visible; everyone done reading Ks

        // ---- O += P @ V (4 rows x 8 dims per thread) ----
#pragma unroll 2
        for (int j = 0; j < BKV; j++) {
            float p[4];
#pragma unroll
            for (int r = 0; r < 4; r++) p[r] = Ps[(ty * 4 + r) * PS_STRIDE + j];
            float4 v0 = *(const float4*)&Vs[j * VS_STRIDE + tx * 8];
            float4 v1 = *(const float4*)&Vs[j * VS_STRIDE + tx * 8 + 4];
            float vv[8] = {v0.x, v0.y, v0.z, v0.w, v1.x, v1.y, v1.z, v1.w};
#pragma unroll
            for (int r = 0; r < 4; r++)
#pragma unroll
                for (int c = 0; c < 8; c++)
                    acc[r][c] = fmaf(p[r], vv[c], acc[r][c]);
        }
        __syncthreads();   // done with Vs/Ps before next tile's loads
    }

    // ---- epilogue: O / l ----
#pragma unroll
    for (int r = 0; r < 4; r++) {
        float inv = 1.0f / l_i[r];
        size_t base = ((size_t)b * T_ + q0 + ty * 4 + r) * HD_ + tx * 8;
        float4 o0 = make_float4(acc[r][0] * inv, acc[r][1] * inv,
                                acc[r][2] * inv, acc[r][3] * inv);
        float4 o1 = make_float4(acc[r][4] * inv, acc[r][5] * inv,
                                acc[r][6] * inv, acc[r][7] * inv);
        *(float4*)(out + base)     = o0;
        *(float4*)(out + base + 4) = o1;
    }
}

// ---------------------------------------------------------------------------
extern "C" void kernel_launch(void* const* d_in, const int* in_sizes, int n_in,
                              void* d_out, int out_size)
{
    const float* x  = (const float*)d_in[0];
    const float* Wq = (const float*)d_in[1];
    const float* Wk = (const float*)d_in[2];
    const float* Wv = (const float*)d_in[3];
    float* out = (float*)d_out;

    (void)in_sizes; (void)n_in; (void)out_size;

    cudaFuncSetAttribute(attn_kernel,
                         cudaFuncAttributeMaxDynamicSharedMemorySize,
                         ATTN_SMEM_BYTES);

    // QKV projections: grid (16384/64, 3)
    qkv_gemm_kernel<<<dim3((B_ * T_) / 64, 3), 256>>>(x, Wq, Wk, Wv);

    // Causal flash attention: grid (T/BQ, B)
    attn_kernel<<<dim3(T_ / BQ, B_), 256, ATTN_SMEM_BYTES>>>(out);
}

// round 4
// speedup vs baseline: 1.3904x; 1.3904x over previous
#include <cuda_runtime.h>
#include <cuda_bf16.h>
#include <math.h>
#include <stdint.h>

#define B_  4
#define T_  4096
#define NE_ 2048
#define HD_ 128
#define M_TOT (B_ * T_)

// ---------------------------------------------------------------------------
// Device scratch (no allocations allowed)
// ---------------------------------------------------------------------------
__device__ float g_Q[M_TOT * HD_];
__device__ float g_K[M_TOT * HD_];
__device__ float g_V[M_TOT * HD_];
// x in bf16 hi/lo, row-major [M_TOT][NE_]
__device__ __nv_bfloat16 g_xhi[(size_t)M_TOT * NE_];
__device__ __nv_bfloat16 g_xlo[(size_t)M_TOT * NE_];
// W^T in bf16 hi/lo: [3][128 n][2048 k]
__device__ __nv_bfloat16 g_wt_hi[3 * HD_ * NE_];
__device__ __nv_bfloat16 g_wt_lo[3 * HD_ * NE_];

// ---------------------------------------------------------------------------
// Kernel 0a: x -> bf16 hi/lo
// ---------------------------------------------------------------------------
__global__ __launch_bounds__(256) void convert_x_kernel(const float* __restrict__ x)
{
    size_t i = ((size_t)blockIdx.x * 256 + threadIdx.x) * 4;
    float4 v = *(const float4*)(x + i);
    __nv_bfloat162 h01 = __floats2bfloat162_rn(v.x, v.y);
    __nv_bfloat162 h23 = __floats2bfloat162_rn(v.z, v.w);
    float lx = v.x - __low2float(h01);
    float ly = v.y - __high2float(h01);
    float lz = v.z - __low2float(h23);
    float lw = v.w - __high2float(h23);
    __nv_bfloat162 l01 = __floats2bfloat162_rn(lx, ly);
    __nv_bfloat162 l23 = __floats2bfloat162_rn(lz, lw);
    *(__nv_bfloat162*)(g_xhi + i)     = h01;
    *(__nv_bfloat162*)(g_xhi + i + 2) = h23;
    *(__nv_bfloat162*)(g_xlo + i)     = l01;
    *(__nv_bfloat162*)(g_xlo + i + 2) = l23;
}

// ---------------------------------------------------------------------------
// Kernel 0b: W -> W^T bf16 hi/lo  (tiny: 3 x 2048 x 128)
// ---------------------------------------------------------------------------
__global__ __launch_bounds__(256) void convert_w_kernel(
    const float* __restrict__ Wq, const float* __restrict__ Wk,
    const float* __restrict__ Wv)
{
    int t = blockIdx.x * 256 + threadIdx.x;
    int o = t / (NE_ * HD_);
    int rem = t - o * (NE_ * HD_);
    int k = rem / HD_;
    int n = rem - k * HD_;
    const float* W = (o == 0) ? Wq : (o == 1) ? Wk : Wv;
    float v = W[(size_t)k * HD_ + n];
    __nv_bfloat16 h = __float2bfloat16(v);
    float lo = v - __bfloat162float(h);
    size_t dst = ((size_t)o * HD_ + n) * NE_ + k;
    g_wt_hi[dst] = h;
    g_wt_lo[dst] = __float2bfloat16(lo);
}

// ---------------------------------------------------------------------------
// Kernel 1: fused QKV projection via mma.sync (HMMA, bf16, fp32 accum).
// grid (3, 128): x = output (Q/K/V), y = 128-row M tile. 256 thr = 8 warps.
// Warp grid 4(m) x 2(n); warp tile m32 x n64. BK = 32. 3-pass hi/lo split.
// ---------------------------------------------------------------------------
#define SA 40   // padded smem k-stride in halves

__device__ __forceinline__ void hmma16816(float* c, const uint32_t* a,
                                          uint32_t b0, uint32_t b1)
{
    asm volatile(
        "mma.sync.aligned.m16n8k16.row.col.f32.bf16.bf16.f32 "
        "{%0,%1,%2,%3}, {%4,%5,%6,%7}, {%8,%9}, {%0,%1,%2,%3};"
        : "+f"(c[0]), "+f"(c[1]), "+f"(c[2]), "+f"(c[3])
        : "r"(a[0]), "r"(a[1]), "r"(a[2]), "r"(a[3]), "r"(b0), "r"(b1));
}

__global__ __launch_bounds__(256, 2) void qkv_hmma_kernel()
{
    __shared__ __nv_bfloat16 A_s[128][SA];
    __shared__ __nv_bfloat16 B_s[128][SA];

    const int o  = blockIdx.x;
    const int m0 = blockIdx.y * 128;
    const int tid  = threadIdx.x;
    const int wid  = tid >> 5;
    const int lane = tid & 31;
    const int wm = wid >> 1;        // 0..3
    const int wn = wid & 1;         // 0..1
    const int g  = lane >> 2;       // 0..7
    const int t  = lane & 3;        // 0..3

    const __nv_bfloat16* Ahi = g_xhi + (size_t)m0 * NE_;
    const __nv_bfloat16* Alo = g_xlo + (size_t)m0 * NE_;
    const __nv_bfloat16* Bhi = g_wt_hi + (size_t)o * HD_ * NE_;
    const __nv_bfloat16* Blo = g_wt_lo + (size_t)o * HD_ * NE_;

    float acc[2][8][4];
#pragma unroll
    for (int mt = 0; mt < 2; mt++)
#pragma unroll
        for (int nt = 0; nt < 8; nt++)
#pragma unroll
            for (int c = 0; c < 4; c++) acc[mt][nt][c] = 0.f;

    const int lr = tid >> 2;            // 0..63 (row within 2-step load)
    const int lk = (tid & 3) * 8;       // 0,8,16,24

#pragma unroll 1
    for (int pass = 0; pass < 3; pass++) {
        const __nv_bfloat16* Ap = (pass == 2) ? Alo : Ahi;
        const __nv_bfloat16* Bp = (pass == 1) ? Blo : Bhi;

#pragma unroll 1
        for (int kb = 0; kb < NE_ / 32; kb++) {
            const int k0 = kb * 32;
            __syncthreads();
#pragma unroll
            for (int q = 0; q < 2; q++) {
                int r = lr + q * 64;
                *(uint4*)&A_s[r][lk] = *(const uint4*)(Ap + (size_t)r * NE_ + k0 + lk);
                *(uint4*)&B_s[r][lk] = *(const uint4*)(Bp + (size_t)r * NE_ + k0 + lk);
            }
            __syncthreads();

#pragma unroll
            for (int ks = 0; ks < 2; ks++) {
                uint32_t a[2][4];
#pragma unroll
                for (int mt = 0; mt < 2; mt++) {
                    const __nv_bfloat16* ab = &A_s[wm * 32 + mt * 16][ks * 16];
                    a[mt][0] = *(const uint32_t*)&ab[(g)     * SA + t * 2];
                    a[mt][1] = *(const uint32_t*)&ab[(g + 8) * SA + t * 2];
                    a[mt][2] = *(const uint32_t*)&ab[(g)     * SA + t * 2 + 8];
                    a[mt][3] = *(const uint32_t*)&ab[(g + 8) * SA + t * 2 + 8];
                }
#pragma unroll
                for (int nt = 0; nt < 8; nt++) {
                    const __nv_bfloat16* bb = &B_s[wn * 64 + nt * 8 + g][ks * 16];
                    uint32_t b0 = *(const uint32_t*)&bb[t * 2];
                    uint32_t b1 = *(const uint32_t*)&bb[t * 2 + 8];
                    hmma16816(acc[0][nt], a[0], b0, b1);
                    hmma16816(acc[1][nt], a[1], b0, b1);
                }
            }
        }
    }

    float* Og = (o == 0) ? g_Q : (o == 1) ? g_K : g_V;
#pragma unroll
    for (int mt = 0; mt < 2; mt++) {
        int row = m0 + wm * 32 + mt * 16 + g;
#pragma unroll
        for (int nt = 0; nt < 8; nt++) {
            int col = wn * 64 + nt * 8 + t * 2;
            *(float2*)(Og + (size_t)row * HD_ + col) =
                make_float2(acc[mt][nt][0], acc[mt][nt][1]);
            *(float2*)(Og + (size_t)(row + 8) * HD_ + col) =
                make_float2(acc[mt][nt][2], acc[mt][nt][3]);
        }
    }
}

// ---------------------------------------------------------------------------
// Kernel 2: causal flash attention, fp32 (unchanged — known good, 919us).
// ---------------------------------------------------------------------------
#define BQ 64
#define BKV 64
#define QS_STRIDE 132
#define KS_STRIDE 129
#define VS_STRIDE 132
#define PS_STRIDE 65

#define ATTN_SMEM_FLOATS (BQ*QS_STRIDE + BKV*KS_STRIDE + BKV*VS_STRIDE + BQ*PS_STRIDE)
#define ATTN_SMEM_BYTES  (ATTN_SMEM_FLOATS * 4)

__global__ __launch_bounds__(256, 1) void attn_kernel(float* __restrict__ out)
{
    extern __shared__ float smf[];
    float* Qs = smf;
    float* Ks = Qs + BQ * QS_STRIDE;
    float* Vs = Ks + BKV * KS_STRIDE;
    float* Ps = Vs + BKV * VS_STRIDE;

    const int b   = blockIdx.y;
    const int qt  = (int)gridDim.x - 1 - (int)blockIdx.x;
    const int q0  = qt * BQ;
    const int tid = threadIdx.x;
    const int tx  = tid & 15;
    const int ty  = tid >> 4;
    const float scale = 0.08838834764831845f;

    const float* Qg = g_Q + (size_t)b * T_ * HD_;
    const float* Kg = g_K + (size_t)b * T_ * HD_;
    const float* Vg = g_V + (size_t)b * T_ * HD_;

    for (int t = tid; t < BQ * 32; t += 256) {
        int r = t >> 5, c4 = (t & 31) << 2;
        float4 v = *(const float4*)(Qg + (size_t)(q0 + r) * HD_ + c4);
        v.x *= scale; v.y *= scale; v.z *= scale; v.w *= scale;
        *(float4*)&Qs[r * QS_STRIDE + c4] = v;
    }

    float m_i[4], l_i[4], acc[4][8];
#pragma unroll
    for (int r = 0; r < 4; r++) {
        m_i[r] = -INFINITY; l_i[r] = 0.f;
#pragma unroll
        for (int c = 0; c < 8; c++) acc[r][c] = 0.f;
    }

    const int nkv = qt + 1;
    for (int kt = 0; kt < nkv; kt++) {
        const int k0 = kt * BKV;
        for (int t = tid; t < BKV * 32; t += 256) {
            int r = t >> 5, c4 = (t & 31) << 2;
            float4 kv = *(const float4*)(Kg + (size_t)(k0 + r) * HD_ + c4);
            Ks[r * KS_STRIDE + c4 + 0] = kv.x;
            Ks[r * KS_STRIDE + c4 + 1] = kv.y;
            Ks[r * KS_STRIDE + c4 + 2] = kv.z;
            Ks[r * KS_STRIDE + c4 + 3] = kv.w;
            float4 vv = *(const float4*)(Vg + (size_t)(k0 + r) * HD_ + c4);
            *(float4*)&Vs[r * VS_STRIDE + c4] = vv;
        }
        __syncthreads();

        float s[4][4];
#pragma unroll
        for (int r = 0; r < 4; r++)
#pragma unroll
            for (int c = 0; c < 4; c++) s[r][c] = 0.f;

#pragma unroll 2
        for (int d = 0; d < HD_; d += 4) {
            float qv[4][4];
#pragma unroll
            for (int r = 0; r < 4; r++) {
                float4 q4 = *(const float4*)&Qs[(ty * 4 + r) * QS_STRIDE + d];
                qv[r][0] = q4.x; qv[r][1] = q4.y; qv[r][2] = q4.z; qv[r][3] = q4.w;
            }
#pragma unroll
            for (int dd = 0; dd < 4; dd++) {
                float kv[4];
#pragma unroll
                for (int c = 0; c < 4; c++)
                    kv[c] = Ks[(tx * 4 + c) * KS_STRIDE + d + dd];
#pragma unroll
                for (int r = 0; r < 4; r++)
#pragma unroll
                    for (int c = 0; c < 4; c++)
                        s[r][c] = fmaf(qv[r][dd], kv[c], s[r][c]);
            }
        }

        if (kt == qt) {
#pragma unroll
            for (int r = 0; r < 4; r++)
#pragma unroll
                for (int c = 0; c < 4; c++)
                    if ((k0 + tx * 4 + c) > (q0 + ty * 4 + r)) s[r][c] = -INFINITY;
        }

        float mnew[4], alpha[4];
#pragma unroll
        for (int r = 0; r < 4; r++) {
            float mx = fmaxf(fmaxf(s[r][0], s[r][1]), fmaxf(s[r][2], s[r][3]));
#pragma unroll
            for (int off = 8; off; off >>= 1)
                mx = fmaxf(mx, __shfl_xor_sync(0xffffffffu, mx, off));
            mnew[r]  = fmaxf(m_i[r], mx);
            alpha[r] = __expf(m_i[r] - mnew[r]);
        }
#pragma unroll
        for (int r = 0; r < 4; r++) {
            float sum = 0.f;
#pragma unroll
            for (int c = 0; c < 4; c++) {
                float p = __expf(s[r][c] - mnew[r]);
                Ps[(ty * 4 + r) * PS_STRIDE + tx * 4 + c] = p;
                sum += p;
            }
#pragma unroll
            for (int off = 8; off; off >>= 1)
                sum += __shfl_xor_sync(0xffffffffu, sum, off);
            l_i[r] = l_i[r] * alpha[r] + sum;
            m_i[r] = mnew[r];
#pragma unroll
            for (int c = 0; c < 8; c++) acc[r][c] *= alpha[r];
        }
        __syncthreads();

#pragma unroll 2
        for (int j = 0; j < BKV; j++) {
            float p[4];
#pragma unroll
            for (int r = 0; r < 4; r++) p[r] = Ps[(ty * 4 + r) * PS_STRIDE + j];
            float4 v0 = *(const float4*)&Vs[j * VS_STRIDE + tx * 8];
            float4 v1 = *(const float4*)&Vs[j * VS_STRIDE + tx * 8 + 4];
            float vv[8] = {v0.x, v0.y, v0.z, v0.w, v1.x, v1.y, v1.z, v1.w};
#pragma unroll
            for (int r = 0; r < 4; r++)
#pragma unroll
                for (int c = 0; c < 8; c++)
                    acc[r][c] = fmaf(p[r], vv[c], acc[r][c]);
        }
        __syncthreads();
    }

#pragma unroll
    for (int r = 0; r < 4; r++) {
        float inv = 1.0f / l_i[r];
        size_t base = ((size_t)b * T_ + q0 + ty * 4 + r) * HD_ + tx * 8;
        float4 o0 = make_float4(acc[r][0] * inv, acc[r][1] * inv,
                                acc[r][2] * inv, acc[r][3] * inv);
        float4 o1 = make_float4(acc[r][4] * inv, acc[r][5] * inv,
                                acc[r][6] * inv, acc[r][7] * inv);
        *(float4*)(out + base)     = o0;
        *(float4*)(out + base + 4) = o1;
    }
}

// ---------------------------------------------------------------------------
extern "C" void kernel_launch(void* const* d_in, const int* in_sizes, int n_in,
                              void* d_out, int out_size)
{
    const float* x  = (const float*)d_in[0];
    const float* Wq = (const float*)d_in[1];
    const float* Wk = (const float*)d_in[2];
    const float* Wv = (const float*)d_in[3];
    float* out = (float*)d_out;
    (void)in_sizes; (void)n_in; (void)out_size;

    cudaFuncSetAttribute(attn_kernel,
                         cudaFuncAttributeMaxDynamicSharedMemorySize, ATTN_SMEM_BYTES);

    // conversions
    convert_x_kernel<<<(M_TOT * (NE_ / 4)) / 256, 256>>>(x);
    convert_w_kernel<<<(3 * NE_ * HD_) / 256, 256>>>(Wq, Wk, Wv);
    // fused QKV projection on HMMA tensor cores
    qkv_hmma_kernel<<<dim3(3, M_TOT / 128), 256>>>();
    // causal flash attention
    attn_kernel<<<dim3(T_ / BQ, B_), 256, ATTN_SMEM_BYTES>>>(out);
}

// round 6
// speedup vs baseline: 2.7908x; 2.0072x over previous
#include <cuda_runtime.h>
#include <cuda_bf16.h>
#include <math.h>
#include <stdint.h>

#define B_  4
#define T_  4096
#define NE_ 2048
#define HD_ 128
#define M_TOT (B_ * T_)

// ---------------------------------------------------------------------------
// Device scratch (no allocations allowed)
// ---------------------------------------------------------------------------
__device__ __nv_bfloat16 g_xhi[(size_t)M_TOT * NE_];
__device__ __nv_bfloat16 g_xlo[(size_t)M_TOT * NE_];
__device__ __nv_bfloat16 g_wt_hi[3 * HD_ * NE_];
__device__ __nv_bfloat16 g_wt_lo[3 * HD_ * NE_];
// projections, bf16 hi/lo. Q pre-scaled by 1/sqrt(128). Vt transposed [B][128][T]
__device__ __nv_bfloat16 g_Qhi[M_TOT * HD_], g_Qlo[M_TOT * HD_];
__device__ __nv_bfloat16 g_Khi[M_TOT * HD_], g_Klo[M_TOT * HD_];
__device__ __nv_bfloat16 g_Vthi[M_TOT * HD_], g_Vtlo[M_TOT * HD_];

// ---------------------------------------------------------------------------
// helpers
// ---------------------------------------------------------------------------
__device__ __forceinline__ void hmma16816(float* c, const uint32_t* a,
                                          uint32_t b0, uint32_t b1)
{
    asm volatile(
        "mma.sync.aligned.m16n8k16.row.col.f32.bf16.bf16.f32 "
        "{%0,%1,%2,%3}, {%4,%5,%6,%7}, {%8,%9}, {%0,%1,%2,%3};"
        : "+f"(c[0]), "+f"(c[1]), "+f"(c[2]), "+f"(c[3])
        : "r"(a[0]), "r"(a[1]), "r"(a[2]), "r"(a[3]), "r"(b0), "r"(b1));
}

__device__ __forceinline__ uint32_t smem_u32(const void* p) {
    uint32_t a;
    asm("{ .reg .u64 t; cvta.to.shared.u64 t, %1; cvt.u32.u64 %0, t; }"
        : "=r"(a) : "l"(p));
    return a;
}

__device__ __forceinline__ void cp_async16(uint32_t dst, const void* src) {
    asm volatile("cp.async.cg.shared.global [%0], [%1], 16;"
                 :: "r"(dst), "l"(src) : "memory");
}

// split two floats into packed bf16x2 hi and lo words
__device__ __forceinline__ void split2(float a, float b, uint32_t& hi, uint32_t& lo) {
    __nv_bfloat162 h = __floats2bfloat162_rn(a, b);
    float ra = a - __low2float(h);
    float rb = b - __high2float(h);
    __nv_bfloat162 l = __floats2bfloat162_rn(ra, rb);
    hi = *(uint32_t*)&h;
    lo = *(uint32_t*)&l;
}

// ---------------------------------------------------------------------------
// Kernel 0a: x -> bf16 hi/lo
// ---------------------------------------------------------------------------
__global__ __launch_bounds__(256) void convert_x_kernel(const float* __restrict__ x)
{
    size_t i = ((size_t)blockIdx.x * 256 + threadIdx.x) * 4;
    float4 v = *(const float4*)(x + i);
    uint32_t h0, l0, h1, l1;
    split2(v.x, v.y, h0, l0);
    split2(v.z, v.w, h1, l1);
    *(uint32_t*)(g_xhi + i)     = h0;
    *(uint32_t*)(g_xhi + i + 2) = h1;
    *(uint32_t*)(g_xlo + i)     = l0;
    *(uint32_t*)(g_xlo + i + 2) = l1;
}

// ---------------------------------------------------------------------------
// Kernel 0b: W -> W^T bf16 hi/lo
// ---------------------------------------------------------------------------
__global__ __launch_bounds__(256) void convert_w_kernel(
    const float* __restrict__ Wq, const float* __restrict__ Wk,
    const float* __restrict__ Wv)
{
    int t = blockIdx.x * 256 + threadIdx.x;
    int o = t / (NE_ * HD_);
    int rem = t - o * (NE_ * HD_);
    int k = rem / HD_;
    int n = rem - k * HD_;
    const float* W = (o == 0) ? Wq : (o == 1) ? Wk : Wv;
    float v = W[(size_t)k * HD_ + n];
    __nv_bfloat16 h = __float2bfloat16(v);
    float lo = v - __bfloat162float(h);
    size_t dst = ((size_t)o * HD_ + n) * NE_ + k;
    g_wt_hi[dst] = h;
    g_wt_lo[dst] = __float2bfloat16(lo);
}

// ---------------------------------------------------------------------------
// Kernel 1: fused QKV projection (HMMA). Epilogue writes bf16 hi/lo:
// o==0 -> Q (scaled), o==1 -> K, o==2 -> V transposed [B][128][T].
// ---------------------------------------------------------------------------
#define SA 40

__global__ __launch_bounds__(256, 2) void qkv_hmma_kernel()
{
    __shared__ __nv_bfloat16 A_s[128][SA];
    __shared__ __nv_bfloat16 B_s[128][SA];

    const int o  = blockIdx.x;
    const int m0 = blockIdx.y * 128;
    const int tid  = threadIdx.x;
    const int wid  = tid >> 5;
    const int lane = tid & 31;
    const int wm = wid >> 1;
    const int wn = wid & 1;
    const int g  = lane >> 2;
    const int t  = lane & 3;

    const __nv_bfloat16* Ahi = g_xhi + (size_t)m0 * NE_;
    const __nv_bfloat16* Alo = g_xlo + (size_t)m0 * NE_;
    const __nv_bfloat16* Bhi = g_wt_hi + (size_t)o * HD_ * NE_;
    const __nv_bfloat16* Blo = g_wt_lo + (size_t)o * HD_ * NE_;

    float acc[2][8][4];
#pragma unroll
    for (int mt = 0; mt < 2; mt++)
#pragma unroll
        for (int nt = 0; nt < 8; nt++)
#pragma unroll
            for (int c = 0; c < 4; c++) acc[mt][nt][c] = 0.f;

    const int lr = tid >> 2;
    const int lk = (tid & 3) * 8;

#pragma unroll 1
    for (int pass = 0; pass < 3; pass++) {
        const __nv_bfloat16* Ap = (pass == 2) ? Alo : Ahi;
        const __nv_bfloat16* Bp = (pass == 1) ? Blo : Bhi;

#pragma unroll 1
        for (int kb = 0; kb < NE_ / 32; kb++) {
            const int k0 = kb * 32;
            __syncthreads();
#pragma unroll
            for (int q = 0; q < 2; q++) {
                int r = lr + q * 64;
                *(uint4*)&A_s[r][lk] = *(const uint4*)(Ap + (size_t)r * NE_ + k0 + lk);
                *(uint4*)&B_s[r][lk] = *(const uint4*)(Bp + (size_t)r * NE_ + k0 + lk);
            }
            __syncthreads();

#pragma unroll
            for (int ks = 0; ks < 2; ks++) {
                uint32_t a[2][4];
#pragma unroll
                for (int mt = 0; mt < 2; mt++) {
                    const __nv_bfloat16* ab = &A_s[wm * 32 + mt * 16][ks * 16];
                    a[mt][0] = *(const uint32_t*)&ab[(g)     * SA + t * 2];
                    a[mt][1] = *(const uint32_t*)&ab[(g + 8) * SA + t * 2];
                    a[mt][2] = *(const uint32_t*)&ab[(g)     * SA + t * 2 + 8];
                    a[mt][3] = *(const uint32_t*)&ab[(g + 8) * SA + t * 2 + 8];
                }
#pragma unroll
                for (int nt = 0; nt < 8; nt++) {
                    const __nv_bfloat16* bb = &B_s[wn * 64 + nt * 8 + g][ks * 16];
                    uint32_t b0 = *(const uint32_t*)&bb[t * 2];
                    uint32_t b1 = *(const uint32_t*)&bb[t * 2 + 8];
                    hmma16816(acc[0][nt], a[0], b0, b1);
                    hmma16816(acc[1][nt], a[1], b0, b1);
                }
            }
        }
    }

    if (o < 2) {
        __nv_bfloat16* Hh = (o == 0) ? g_Qhi : g_Khi;
        __nv_bfloat16* Hl = (o == 0) ? g_Qlo : g_Klo;
        const float sc = (o == 0) ? 0.08838834764831845f : 1.0f;
#pragma unroll
        for (int mt = 0; mt < 2; mt++) {
            int row = m0 + wm * 32 + mt * 16 + g;
#pragma unroll
            for (int nt = 0; nt < 8; nt++) {
                int col = wn * 64 + nt * 8 + t * 2;
                uint32_t h0, l0, h1, l1;
                split2(acc[mt][nt][0] * sc, acc[mt][nt][1] * sc, h0, l0);
                split2(acc[mt][nt][2] * sc, acc[mt][nt][3] * sc, h1, l1);
                *(uint32_t*)&Hh[(size_t)row * HD_ + col] = h0;
                *(uint32_t*)&Hl[(size_t)row * HD_ + col] = l0;
                *(uint32_t*)&Hh[(size_t)(row + 8) * HD_ + col] = h1;
                *(uint32_t*)&Hl[(size_t)(row + 8) * HD_ + col] = l1;
            }
        }
    } else {
        // V transposed: [B][128 hd][T tokens]
#pragma unroll
        for (int mt = 0; mt < 2; mt++) {
            int rowa = m0 + wm * 32 + mt * 16 + g;
            int bidx = rowa >> 12;
            int tok  = rowa & (T_ - 1);
#pragma unroll
            for (int nt = 0; nt < 8; nt++) {
                int col = wn * 64 + nt * 8 + t * 2;
#pragma unroll
                for (int cc = 0; cc < 2; cc++) {
                    float v0 = acc[mt][nt][cc];
                    float v1 = acc[mt][nt][2 + cc];
                    __nv_bfloat16 h0 = __float2bfloat16(v0);
                    __nv_bfloat16 h1 = __float2bfloat16(v1);
                    size_t base = ((size_t)bidx * HD_ + col + cc) * T_;
                    g_Vthi[base + tok]     = h0;
                    g_Vtlo[base + tok]     = __float2bfloat16(v0 - __bfloat162float(h0));
                    g_Vthi[base + tok + 8] = h1;
                    g_Vtlo[base + tok + 8] = __float2bfloat16(v1 - __bfloat162float(h1));
                }
            }
        }
    }
}

// ---------------------------------------------------------------------------
// Kernel 2: causal flash attention on HMMA.
// CTA = 256 thr = 2 groups x 4 warps. Group A: q-tile p; group B: q-tile 63-p
// (folded pairing -> every CTA does exactly 64 kv-iterations).
// BQ = BKV = 64. K/V double-buffered via cp.async.
// ---------------------------------------------------------------------------
#define SAK 136
#define SAV 72
#define Q_GRP_ELL (64 * SAK)              // 8704
#define OFF_QHI 0
#define OFF_QLO (2 * Q_GRP_ELL)           // 17408
#define OFF_K   (4 * Q_GRP_ELL)           // 34816
#define K_STAGE (2 * 64 * SAK)            // 17408 (hi+lo)
#define OFF_V   (OFF_K + 2 * K_STAGE)     // 69632
#define V_HALF  (128 * SAV)               // 9216
#define V_STAGE (2 * V_HALF)              // 18432
#define ATTN_SMEM_ELL (OFF_V + 2 * V_STAGE)   // 106496 elems
#define ATTN_SMEM_B   (ATTN_SMEM_ELL * 2)     // 212992 bytes

__device__ __forceinline__ void load_kv_tile(int b, int kt, int st, int tid,
                                             uint32_t sbu)
{
#pragma unroll
    for (int i = 0; i < 8; i++) {
        int c = tid + i * 256;                // 0..2047
        int arr = c >> 10, idx = c & 1023;
        int r = idx >> 4, ch = (idx & 15) * 8;
        const __nv_bfloat16* src = (arr ? g_Klo : g_Khi)
            + ((size_t)(b * T_ + kt * 64 + r)) * HD_ + ch;
        uint32_t dst = sbu + (uint32_t)(OFF_K + st * K_STAGE + arr * (64 * SAK)
                                        + r * SAK + ch) * 2;
        cp_async16(dst, src);
    }
#pragma unroll
    for (int i = 0; i < 8; i++) {
        int c = tid + i * 256;
        int arr = c >> 10, idx = c & 1023;
        int hd = idx >> 3, ch = (idx & 7) * 8;
        const __nv_bfloat16* src = (arr ? g_Vtlo : g_Vthi)
            + ((size_t)b * HD_ + hd) * T_ + kt * 64 + ch;
        uint32_t dst = sbu + (uint32_t)(OFF_V + st * V_STAGE + arr * V_HALF
                                        + hd * SAV + ch) * 2;
        cp_async16(dst, src);
    }
    asm volatile("cp.async.commit_group;" ::: "memory");
}

__global__ __launch_bounds__(256, 1) void attn_hmma_kernel(float* __restrict__ out)
{
    extern __shared__ __nv_bfloat16 sb[];
    const uint32_t sbu = smem_u32(sb);
    const int b   = blockIdx.y;
    const int p   = blockIdx.x;                 // folded pair index 0..31
    const int tid = threadIdx.x;
    const int wid = tid >> 5, lane = tid & 31;
    const int g   = lane >> 2, t = lane & 3;
    const int grp = wid >> 2, wm = wid & 3;
    const int qt   = grp ? (63 - p) : p;
    const int kmax = 63 - p;
    const int q0   = qt * 64;

    // prefetch first K/V tile
    load_kv_tile(b, 0, 0, tid, sbu);

    // load both groups' Q tiles (hi/lo) into smem: 64 rows x 128 cols each
    {
        const int qrow[2] = { p * 64, (63 - p) * 64 };
#pragma unroll
        for (int i = 0; i < 16; i++) {
            int c = tid + i * 256;                    // 0..4095
            int arr = c >> 11, rem = c & 2047;
            int gg = rem >> 10, rem2 = rem & 1023;
            int r = rem2 >> 4, c8 = (rem2 & 15) * 8;  // 64 rows x 16 chunks
            const __nv_bfloat16* src = (arr ? g_Qlo : g_Qhi)
                + ((size_t)(b * T_ + qrow[gg] + r)) * HD_ + c8;
            int dst = (arr ? OFF_QLO : OFF_QHI) + gg * Q_GRP_ELL + r * SAK + c8;
            *(uint4*)&sb[dst] = *(const uint4*)src;
        }
    }
    __syncthreads();

    // hoist Q-hi a-frags (tile-invariant); Q-lo loaded from smem per tile
    uint32_t qa_hi[8][4];
    const __nv_bfloat16* Qh = sb + OFF_QHI + grp * Q_GRP_ELL + wm * 16 * SAK;
    const __nv_bfloat16* Ql = sb + OFF_QLO + grp * Q_GRP_ELL + wm * 16 * SAK;
#pragma unroll
    for (int ks = 0; ks < 8; ks++) {
        const __nv_bfloat16* ah = Qh + ks * 16;
        qa_hi[ks][0] = *(const uint32_t*)&ah[(g)     * SAK + t * 2];
        qa_hi[ks][1] = *(const uint32_t*)&ah[(g + 8) * SAK + t * 2];
        qa_hi[ks][2] = *(const uint32_t*)&ah[(g)     * SAK + t * 2 + 8];
        qa_hi[ks][3] = *(const uint32_t*)&ah[(g + 8) * SAK + t * 2 + 8];
    }

    float m0r = -INFINITY, m1r = -INFINITY, l0r = 0.f, l1r = 0.f;
    float oacc[16][4];
#pragma unroll
    for (int nf = 0; nf < 16; nf++)
#pragma unroll
        for (int c = 0; c < 4; c++) oacc[nf][c] = 0.f;

#pragma unroll 1
    for (int kt = 0; kt <= kmax; kt++) {
        const int st = kt & 1;
        if (kt < kmax) {
            load_kv_tile(b, kt + 1, st ^ 1, tid, sbu);
            asm volatile("cp.async.wait_group 1;" ::: "memory");
        } else {
            asm volatile("cp.async.wait_group 0;" ::: "memory");
        }
        __syncthreads();

        if (kt <= qt) {
            const __nv_bfloat16* Kh = sb + OFF_K + st * K_STAGE;
            const __nv_bfloat16* Kl = Kh + 64 * SAK;
            const __nv_bfloat16* Vh = sb + OFF_V + st * V_STAGE;
            const __nv_bfloat16* Vl = Vh + V_HALF;

            // ---- S = Qhi*Khi + Qhi*Klo + Qlo*Khi ----
            float sacc[8][4];
#pragma unroll
            for (int nf = 0; nf < 8; nf++)
#pragma unroll
                for (int c = 0; c < 4; c++) sacc[nf][c] = 0.f;

#pragma unroll
            for (int pp = 0; pp < 2; pp++) {
                const __nv_bfloat16* Kp = pp ? Kl : Kh;
#pragma unroll
                for (int ks = 0; ks < 8; ks++) {
#pragma unroll
                    for (int nf = 0; nf < 8; nf++) {
                        const __nv_bfloat16* bb = Kp + (nf * 8 + g) * SAK
                                                     + ks * 16 + t * 2;
                        hmma16816(sacc[nf], qa_hi[ks],
                                  *(const uint32_t*)bb, *(const uint32_t*)(bb + 8));
                    }
                }
            }
#pragma unroll
            for (int ks = 0; ks < 8; ks++) {
                uint32_t a[4];
                const __nv_bfloat16* al = Ql + ks * 16;
                a[0] = *(const uint32_t*)&al[(g)     * SAK + t * 2];
                a[1] = *(const uint32_t*)&al[(g + 8) * SAK + t * 2];
                a[2] = *(const uint32_t*)&al[(g)     * SAK + t * 2 + 8];
                a[3] = *(const uint32_t*)&al[(g + 8) * SAK + t * 2 + 8];
#pragma unroll
                for (int nf = 0; nf < 8; nf++) {
                    const __nv_bfloat16* bb = Kh + (nf * 8 + g) * SAK
                                                 + ks * 16 + t * 2;
                    hmma16816(sacc[nf], a,
                              *(const uint32_t*)bb, *(const uint32_t*)(bb + 8));
                }
            }

            // ---- causal mask (diagonal tile only) ----
            if (kt == qt) {
                const int row0 = q0 + wm * 16 + g;
#pragma unroll
                for (int nf = 0; nf < 8; nf++) {
                    int col = kt * 64 + nf * 8 + t * 2;
                    if (col     > row0)     sacc[nf][0] = -INFINITY;
                    if (col + 1 > row0)     sacc[nf][1] = -INFINITY;
                    if (col     > row0 + 8) sacc[nf][2] = -INFINITY;
                    if (col + 1 > row0 + 8) sacc[nf][3] = -INFINITY;
                }
            }

            // ---- online softmax ----
            float mx0 = -INFINITY, mx1 = -INFINITY;
#pragma unroll
            for (int nf = 0; nf < 8; nf++) {
                mx0 = fmaxf(mx0, fmaxf(sacc[nf][0], sacc[nf][1]));
                mx1 = fmaxf(mx1, fmaxf(sacc[nf][2], sacc[nf][3]));
            }
            mx0 = fmaxf(mx0, __shfl_xor_sync(0xffffffffu, mx0, 1));
            mx0 = fmaxf(mx0, __shfl_xor_sync(0xffffffffu, mx0, 2));
            mx1 = fmaxf(mx1, __shfl_xor_sync(0xffffffffu, mx1, 1));
            mx1 = fmaxf(mx1, __shfl_xor_sync(0xffffffffu, mx1, 2));
            float mn0 = fmaxf(m0r, mx0), mn1 = fmaxf(m1r, mx1);
            float al0 = __expf(m0r - mn0), al1 = __expf(m1r - mn1);
            m0r = mn0; m1r = mn1;

            float s0 = 0.f, s1 = 0.f;
            uint32_t ph0[8], ph1[8], pl0[8], pl1[8];
#pragma unroll
            for (int nf = 0; nf < 8; nf++) {
                float p00 = __expf(sacc[nf][0] - mn0);
                float p01 = __expf(sacc[nf][1] - mn0);
                float p10 = __expf(sacc[nf][2] - mn1);
                float p11 = __expf(sacc[nf][3] - mn1);
                s0 += p00 + p01;
                s1 += p10 + p11;
                split2(p00, p01, ph0[nf], pl0[nf]);
                split2(p10, p11, ph1[nf], pl1[nf]);
            }
            s0 += __shfl_xor_sync(0xffffffffu, s0, 1);
            s0 += __shfl_xor_sync(0xffffffffu, s0, 2);
            s1 += __shfl_xor_sync(0xffffffffu, s1, 1);
            s1 += __shfl_xor_sync(0xffffffffu, s1, 2);
            l0r = l0r * al0 + s0;
            l1r = l1r * al1 + s1;

#pragma unroll
            for (int nf = 0; nf < 16; nf++) {
                oacc[nf][0] *= al0; oacc[nf][1] *= al0;
                oacc[nf][2] *= al1; oacc[nf][3] *= al1;
            }

            // ---- O += Phi*Vhi + Phi*Vlo + Plo*Vhi ----
#pragma unroll
            for (int pp = 0; pp < 2; pp++) {
                const __nv_bfloat16* Vp = pp ? Vl : Vh;
#pragma unroll
                for (int kk = 0; kk < 4; kk++) {
                    uint32_t a[4] = { ph0[2 * kk], ph1[2 * kk],
                                      ph0[2 * kk + 1], ph1[2 * kk + 1] };
#pragma unroll
                    for (int nf = 0; nf < 16; nf++) {
                        const __nv_bfloat16* bb = Vp + (nf * 8 + g) * SAV
                                                     + kk * 16 + t * 2;
                        hmma16816(oacc[nf], a,
                                  *(const uint32_t*)bb, *(const uint32_t*)(bb + 8));
                    }
                }
            }
#pragma unroll
            for (int kk = 0; kk < 4; kk++) {
                uint32_t a[4] = { pl0[2 * kk], pl1[2 * kk],
                                  pl0[2 * kk + 1], pl1[2 * kk + 1] };
#pragma unroll
                for (int nf = 0; nf < 16; nf++) {
                    const __nv_bfloat16* bb = Vh + (nf * 8 + g) * SAV
                                                 + kk * 16 + t * 2;
                    hmma16816(oacc[nf], a,
                              *(const uint32_t*)bb, *(const uint32_t*)(bb + 8));
                }
            }
        }
        __syncthreads();
    }

    // ---- epilogue ----
    const float i0 = 1.0f / l0r, i1 = 1.0f / l1r;
    const int row0 = b * T_ + q0 + wm * 16 + g;
#pragma unroll
    for (int nf = 0; nf < 16; nf++) {
        int col = nf * 8 + t * 2;
        *(float2*)&out[(size_t)row0 * HD_ + col] =
            make_float2(oacc[nf][0] * i0, oacc[nf][1] * i0);
        *(float2*)&out[(size_t)(row0 + 8) * HD_ + col] =
            make_float2(oacc[nf][2] * i1, oacc[nf][3] * i1);
    }
}

// ---------------------------------------------------------------------------
extern "C" void kernel_launch(void* const* d_in, const int* in_sizes, int n_in,
                              void* d_out, int out_size)
{
    const float* x  = (const float*)d_in[0];
    const float* Wq = (const float*)d_in[1];
    const float* Wk = (const float*)d_in[2];
    const float* Wv = (const float*)d_in[3];
    float* out = (float*)d_out;
    (void)in_sizes; (void)n_in; (void)out_size;

    cudaFuncSetAttribute(attn_hmma_kernel,
                         cudaFuncAttributeMaxDynamicSharedMemorySize, ATTN_SMEM_B);

    convert_x_kernel<<<(M_TOT * (NE_ / 4)) / 256, 256>>>(x);
    convert_w_kernel<<<(3 * NE_ * HD_) / 256, 256>>>(Wq, Wk, Wv);
    qkv_hmma_kernel<<<dim3(3, M_TOT / 128), 256>>>();
    attn_hmma_kernel<<<dim3(32, B_), 256, ATTN_SMEM_B>>>(out);
}

// round 7
// speedup vs baseline: 3.6463x; 1.3065x over previous
#include <cuda_runtime.h>
#include <cuda_bf16.h>
#include <math.h>
#include <stdint.h>

#define B_  4
#define T_  4096
#define NE_ 2048
#define HD_ 128
#define M_TOT (B_ * T_)

// ---------------------------------------------------------------------------
// Device scratch (no allocations allowed)
// ---------------------------------------------------------------------------
__device__ __nv_bfloat16 g_xhi[(size_t)M_TOT * NE_];
__device__ __nv_bfloat16 g_xlo[(size_t)M_TOT * NE_];
__device__ __nv_bfloat16 g_wt_hi[3 * HD_ * NE_];
__device__ __nv_bfloat16 g_wt_lo[3 * HD_ * NE_];
// projections, bf16 hi/lo. Q pre-scaled by 1/sqrt(128). Vt transposed [B][128][T]
__device__ __nv_bfloat16 g_Qhi[M_TOT * HD_], g_Qlo[M_TOT * HD_];
__device__ __nv_bfloat16 g_Khi[M_TOT * HD_], g_Klo[M_TOT * HD_];
__device__ __nv_bfloat16 g_Vthi[M_TOT * HD_], g_Vtlo[M_TOT * HD_];

// ---------------------------------------------------------------------------
// helpers
// ---------------------------------------------------------------------------
__device__ __forceinline__ void hmma16816(float* c, const uint32_t* a,
                                          uint32_t b0, uint32_t b1)
{
    asm volatile(
        "mma.sync.aligned.m16n8k16.row.col.f32.bf16.bf16.f32 "
        "{%0,%1,%2,%3}, {%4,%5,%6,%7}, {%8,%9}, {%0,%1,%2,%3};"
        : "+f"(c[0]), "+f"(c[1]), "+f"(c[2]), "+f"(c[3])
        : "r"(a[0]), "r"(a[1]), "r"(a[2]), "r"(a[3]), "r"(b0), "r"(b1));
}

__device__ __forceinline__ uint32_t smem_u32(const void* p) {
    uint32_t a;
    asm("{ .reg .u64 t; cvta.to.shared.u64 t, %1; cvt.u32.u64 %0, t; }"
        : "=r"(a) : "l"(p));
    return a;
}

__device__ __forceinline__ void cp_async16(uint32_t dst, const void* src) {
    asm volatile("cp.async.cg.shared.global [%0], [%1], 16;"
                 :: "r"(dst), "l"(src) : "memory");
}

__device__ __forceinline__ void split2(float a, float b, uint32_t& hi, uint32_t& lo) {
    __nv_bfloat162 h = __floats2bfloat162_rn(a, b);
    float ra = a - __low2float(h);
    float rb = b - __high2float(h);
    __nv_bfloat162 l = __floats2bfloat162_rn(ra, rb);
    hi = *(uint32_t*)&h;
    lo = *(uint32_t*)&l;
}

// ---------------------------------------------------------------------------
// Kernel 0a: x -> bf16 hi/lo
// ---------------------------------------------------------------------------
__global__ __launch_bounds__(256) void convert_x_kernel(const float* __restrict__ x)
{
    size_t i = ((size_t)blockIdx.x * 256 + threadIdx.x) * 4;
    float4 v = *(const float4*)(x + i);
    uint32_t h0, l0, h1, l1;
    split2(v.x, v.y, h0, l0);
    split2(v.z, v.w, h1, l1);
    *(uint32_t*)(g_xhi + i)     = h0;
    *(uint32_t*)(g_xhi + i + 2) = h1;
    *(uint32_t*)(g_xlo + i)     = l0;
    *(uint32_t*)(g_xlo + i + 2) = l1;
}

// ---------------------------------------------------------------------------
// Kernel 0b: W -> W^T bf16 hi/lo
// ---------------------------------------------------------------------------
__global__ __launch_bounds__(256) void convert_w_kernel(
    const float* __restrict__ Wq, const float* __restrict__ Wk,
    const float* __restrict__ Wv)
{
    int t = blockIdx.x * 256 + threadIdx.x;
    int o = t / (NE_ * HD_);
    int rem = t - o * (NE_ * HD_);
    int k = rem / HD_;
    int n = rem - k * HD_;
    const float* W = (o == 0) ? Wq : (o == 1) ? Wk : Wv;
    float v = W[(size_t)k * HD_ + n];
    __nv_bfloat16 h = __float2bfloat16(v);
    float lo = v - __bfloat162float(h);
    size_t dst = ((size_t)o * HD_ + n) * NE_ + k;
    g_wt_hi[dst] = h;
    g_wt_lo[dst] = __float2bfloat16(lo);
}

// ---------------------------------------------------------------------------
// Kernel 1: fused QKV projection (HMMA), cp.async double-buffered, 3-pass
// split fused per k-block. grid (3, 128). Epilogue: Q/K hi/lo direct,
// V transposed via smem (coalesced).
// ---------------------------------------------------------------------------
#define SA 40
#define TILE_ELL (128 * SA)                 // 5120 halves per tile
#define STAGE_ELL (4 * TILE_ELL)            // Ahi,Alo,Bhi,Blo = 20480 halves
#define QKV_SMEM_B 81920                    // 2 stages * 40960 B
#define SVT 136                             // fp32 transpose stride

__device__ __forceinline__ void qkv_load_kb(const __nv_bfloat16* Ahi,
                                            const __nv_bfloat16* Alo,
                                            const __nv_bfloat16* Bhi,
                                            const __nv_bfloat16* Blo,
                                            int k0, int st, int tid, uint32_t sbu)
{
    const __nv_bfloat16* srcs[4] = { Ahi, Alo, Bhi, Blo };
#pragma unroll
    for (int i = 0; i < 8; i++) {
        int c = tid + i * 256;               // 0..2047
        int arr = c >> 9, idx = c & 511;
        int r = idx >> 2, ch = (idx & 3) * 8;
        const __nv_bfloat16* src = srcs[arr] + (size_t)r * NE_ + k0 + ch;
        uint32_t dst = sbu + (uint32_t)(st * STAGE_ELL + arr * TILE_ELL
                                        + r * SA + ch) * 2;
        cp_async16(dst, src);
    }
    asm volatile("cp.async.commit_group;" ::: "memory");
}

__global__ __launch_bounds__(256, 2) void qkv_hmma_kernel()
{
    extern __shared__ __nv_bfloat16 qs[];
    const uint32_t sbu = smem_u32(qs);

    const int o  = blockIdx.x;
    const int m0 = blockIdx.y * 128;
    const int tid  = threadIdx.x;
    const int wid  = tid >> 5;
    const int lane = tid & 31;
    const int wm = wid >> 1;
    const int wn = wid & 1;
    const int g  = lane >> 2;
    const int t  = lane & 3;

    const __nv_bfloat16* Ahi = g_xhi + (size_t)m0 * NE_;
    const __nv_bfloat16* Alo = g_xlo + (size_t)m0 * NE_;
    const __nv_bfloat16* Bhi = g_wt_hi + (size_t)o * HD_ * NE_;
    const __nv_bfloat16* Blo = g_wt_lo + (size_t)o * HD_ * NE_;

    float acc[2][8][4];
#pragma unroll
    for (int mt = 0; mt < 2; mt++)
#pragma unroll
        for (int nt = 0; nt < 8; nt++)
#pragma unroll
            for (int c = 0; c < 4; c++) acc[mt][nt][c] = 0.f;

    qkv_load_kb(Ahi, Alo, Bhi, Blo, 0, 0, tid, sbu);

#pragma unroll 1
    for (int kb = 0; kb < NE_ / 32; kb++) {
        const int st = kb & 1;
        if (kb < NE_ / 32 - 1) {
            qkv_load_kb(Ahi, Alo, Bhi, Blo, (kb + 1) * 32, st ^ 1, tid, sbu);
            asm volatile("cp.async.wait_group 1;" ::: "memory");
        } else {
            asm volatile("cp.async.wait_group 0;" ::: "memory");
        }
        __syncthreads();

        const __nv_bfloat16* sAh = qs + st * STAGE_ELL;
        const __nv_bfloat16* sAl = sAh + TILE_ELL;
        const __nv_bfloat16* sBh = sAh + 2 * TILE_ELL;
        const __nv_bfloat16* sBl = sAh + 3 * TILE_ELL;

#pragma unroll
        for (int ks = 0; ks < 2; ks++) {
            uint32_t a[2][4];
            // --- A-hi frags (shared by passes 0 and 1) ---
#pragma unroll
            for (int mt = 0; mt < 2; mt++) {
                const __nv_bfloat16* ab = sAh + (wm * 32 + mt * 16) * SA + ks * 16;
                a[mt][0] = *(const uint32_t*)&ab[(g)     * SA + t * 2];
                a[mt][1] = *(const uint32_t*)&ab[(g + 8) * SA + t * 2];
                a[mt][2] = *(const uint32_t*)&ab[(g)     * SA + t * 2 + 8];
                a[mt][3] = *(const uint32_t*)&ab[(g + 8) * SA + t * 2 + 8];
            }
#pragma unroll
            for (int nt = 0; nt < 8; nt++) {    // pass 0: Ahi*Bhi
                const __nv_bfloat16* bb = sBh + (wn * 64 + nt * 8 + g) * SA + ks * 16;
                uint32_t b0 = *(const uint32_t*)&bb[t * 2];
                uint32_t b1 = *(const uint32_t*)&bb[t * 2 + 8];
                hmma16816(acc[0][nt], a[0], b0, b1);
                hmma16816(acc[1][nt], a[1], b0, b1);
            }
#pragma unroll
            for (int nt = 0; nt < 8; nt++) {    // pass 1: Ahi*Blo
                const __nv_bfloat16* bb = sBl + (wn * 64 + nt * 8 + g) * SA + ks * 16;
                uint32_t b0 = *(const uint32_t*)&bb[t * 2];
                uint32_t b1 = *(const uint32_t*)&bb[t * 2 + 8];
                hmma16816(acc[0][nt], a[0], b0, b1);
                hmma16816(acc[1][nt], a[1], b0, b1);
            }
            // --- A-lo frags (pass 2) ---
#pragma unroll
            for (int mt = 0; mt < 2; mt++) {
                const __nv_bfloat16* ab = sAl + (wm * 32 + mt * 16) * SA + ks * 16;
                a[mt][0] = *(const uint32_t*)&ab[(g)     * SA + t * 2];
                a[mt][1] = *(const uint32_t*)&ab[(g + 8) * SA + t * 2];
                a[mt][2] = *(const uint32_t*)&ab[(g)     * SA + t * 2 + 8];
                a[mt][3] = *(const uint32_t*)&ab[(g + 8) * SA + t * 2 + 8];
            }
#pragma unroll
            for (int nt = 0; nt < 8; nt++) {    // pass 2: Alo*Bhi
                const __nv_bfloat16* bb = sBh + (wn * 64 + nt * 8 + g) * SA + ks * 16;
                uint32_t b0 = *(const uint32_t*)&bb[t * 2];
                uint32_t b1 = *(const uint32_t*)&bb[t * 2 + 8];
                hmma16816(acc[0][nt], a[0], b0, b1);
                hmma16816(acc[1][nt], a[1], b0, b1);
            }
        }
        __syncthreads();
    }

    if (o < 2) {
        __nv_bfloat16* Hh = (o == 0) ? g_Qhi : g_Khi;
        __nv_bfloat16* Hl = (o == 0) ? g_Qlo : g_Klo;
        const float sc = (o == 0) ? 0.08838834764831845f : 1.0f;
#pragma unroll
        for (int mt = 0; mt < 2; mt++) {
            int row = m0 + wm * 32 + mt * 16 + g;
#pragma unroll
            for (int nt = 0; nt < 8; nt++) {
                int col = wn * 64 + nt * 8 + t * 2;
                uint32_t h0, l0, h1, l1;
                split2(acc[mt][nt][0] * sc, acc[mt][nt][1] * sc, h0, l0);
                split2(acc[mt][nt][2] * sc, acc[mt][nt][3] * sc, h1, l1);
                *(uint32_t*)&Hh[(size_t)row * HD_ + col] = h0;
                *(uint32_t*)&Hl[(size_t)row * HD_ + col] = l0;
                *(uint32_t*)&Hh[(size_t)(row + 8) * HD_ + col] = h1;
                *(uint32_t*)&Hl[(size_t)(row + 8) * HD_ + col] = l1;
            }
        }
    } else {
        // V: transpose via smem, then coalesced hi/lo stores to [B][128][T]
        float* sT = (float*)qs;     // [128 col][SVT] fp32, 69632 B < 81920
#pragma unroll
        for (int mt = 0; mt < 2; mt++) {
            int row = wm * 32 + mt * 16 + g;
#pragma unroll
            for (int nt = 0; nt < 8; nt++) {
                int col = wn * 64 + nt * 8 + t * 2;
                sT[(col)     * SVT + row]     = acc[mt][nt][0];
                sT[(col + 1) * SVT + row]     = acc[mt][nt][1];
                sT[(col)     * SVT + row + 8] = acc[mt][nt][2];
                sT[(col + 1) * SVT + row + 8] = acc[mt][nt][3];
            }
        }
        __syncthreads();
        const int bidx = m0 >> 12;
        const int tok0 = m0 & (T_ - 1);
#pragma unroll
        for (int i = 0; i < 8; i++) {
            int c = tid + i * 256;              // 0..2047
            int hd = c >> 4, ch = (c & 15) * 8;
            const float* srcr = sT + hd * SVT + ch;
            uint32_t h[4], l[4];
#pragma unroll
            for (int q = 0; q < 4; q++)
                split2(srcr[q * 2], srcr[q * 2 + 1], h[q], l[q]);
            size_t base = ((size_t)bidx * HD_ + hd) * T_ + tok0 + ch;
            *(uint4*)(g_Vthi + base) = make_uint4(h[0], h[1], h[2], h[3]);
            *(uint4*)(g_Vtlo + base) = make_uint4(l[0], l[1], l[2], l[3]);
        }
    }
}

// ---------------------------------------------------------------------------
// Kernel 2: causal flash attention on HMMA (unchanged — 210us, known good).
// ---------------------------------------------------------------------------
#define SAK 136
#define SAV 72
#define Q_GRP_ELL (64 * SAK)
#define OFF_QHI 0
#define OFF_QLO (2 * Q_GRP_ELL)
#define OFF_K   (4 * Q_GRP_ELL)
#define K_STAGE (2 * 64 * SAK)
#define OFF_V   (OFF_K + 2 * K_STAGE)
#define V_HALF  (128 * SAV)
#define V_STAGE (2 * V_HALF)
#define ATTN_SMEM_ELL (OFF_V + 2 * V_STAGE)
#define ATTN_SMEM_B   (ATTN_SMEM_ELL * 2)

__device__ __forceinline__ void load_kv_tile(int b, int kt, int st, int tid,
                                             uint32_t sbu)
{
#pragma unroll
    for (int i = 0; i < 8; i++) {
        int c = tid + i * 256;
        int arr = c >> 10, idx = c & 1023;
        int r = idx >> 4, ch = (idx & 15) * 8;
        const __nv_bfloat16* src = (arr ? g_Klo : g_Khi)
            + ((size_t)(b * T_ + kt * 64 + r)) * HD_ + ch;
        uint32_t dst = sbu + (uint32_t)(OFF_K + st * K_STAGE + arr * (64 * SAK)
                                        + r * SAK + ch) * 2;
        cp_async16(dst, src);
    }
#pragma unroll
    for (int i = 0; i < 8; i++) {
        int c = tid + i * 256;
        int arr = c >> 10, idx = c & 1023;
        int hd = idx >> 3, ch = (idx & 7) * 8;
        const __nv_bfloat16* src = (arr ? g_Vtlo : g_Vthi)
            + ((size_t)b * HD_ + hd) * T_ + kt * 64 + ch;
        uint32_t dst = sbu + (uint32_t)(OFF_V + st * V_STAGE + arr * V_HALF
                                        + hd * SAV + ch) * 2;
        cp_async16(dst, src);
    }
    asm volatile("cp.async.commit_group;" ::: "memory");
}

__global__ __launch_bounds__(256, 1) void attn_hmma_kernel(float* __restrict__ out)
{
    extern __shared__ __nv_bfloat16 sb[];
    const uint32_t sbu = smem_u32(sb);
    const int b   = blockIdx.y;
    const int p   = blockIdx.x;
    const int tid = threadIdx.x;
    const int wid = tid >> 5, lane = tid & 31;
    const int g   = lane >> 2, t = lane & 3;
    const int grp = wid >> 2, wm = wid & 3;
    const int qt   = grp ? (63 - p) : p;
    const int kmax = 63 - p;
    const int q0   = qt * 64;

    load_kv_tile(b, 0, 0, tid, sbu);

    {
        const int qrow[2] = { p * 64, (63 - p) * 64 };
#pragma unroll
        for (int i = 0; i < 16; i++) {
            int c = tid + i * 256;
            int arr = c >> 11, rem = c & 2047;
            int gg = rem >> 10, rem2 = rem & 1023;
            int r = rem2 >> 4, c8 = (rem2 & 15) * 8;
            const __nv_bfloat16* src = (arr ? g_Qlo : g_Qhi)
                + ((size_t)(b * T_ + qrow[gg] + r)) * HD_ + c8;
            int dst = (arr ? OFF_QLO : OFF_QHI) + gg * Q_GRP_ELL + r * SAK + c8;
            *(uint4*)&sb[dst] = *(const uint4*)src;
        }
    }
    __syncthreads();

    uint32_t qa_hi[8][4];
    const __nv_bfloat16* Qh = sb + OFF_QHI + grp * Q_GRP_ELL + wm * 16 * SAK;
    const __nv_bfloat16* Ql = sb + OFF_QLO + grp * Q_GRP_ELL + wm * 16 * SAK;
#pragma unroll
    for (int ks = 0; ks < 8; ks++) {
        const __nv_bfloat16* ah = Qh + ks * 16;
        qa_hi[ks][0] = *(const uint32_t*)&ah[(g)     * SAK + t * 2];
        qa_hi[ks][1] = *(const uint32_t*)&ah[(g + 8) * SAK + t * 2];
        qa_hi[ks][2] = *(const uint32_t*)&ah[(g)     * SAK + t * 2 + 8];
        qa_hi[ks][3] = *(const uint32_t*)&ah[(g + 8) * SAK + t * 2 + 8];
    }

    float m0r = -INFINITY, m1r = -INFINITY, l0r = 0.f, l1r = 0.f;
    float oacc[16][4];
#pragma unroll
    for (int nf = 0; nf < 16; nf++)
#pragma unroll
        for (int c = 0; c < 4; c++) oacc[nf][c] = 0.f;

#pragma unroll 1
    for (int kt = 0; kt <= kmax; kt++) {
        const int st = kt & 1;
        if (kt < kmax) {
            load_kv_tile(b, kt + 1, st ^ 1, tid, sbu);
            asm volatile("cp.async.wait_group 1;" ::: "memory");
        } else {
            asm volatile("cp.async.wait_group 0;" ::: "memory");
        }
        __syncthreads();

        if (kt <= qt) {
            const __nv_bfloat16* Kh = sb + OFF_K + st * K_STAGE;
            const __nv_bfloat16* Kl = Kh + 64 * SAK;
            const __nv_bfloat16* Vh = sb + OFF_V + st * V_STAGE;
            const __nv_bfloat16* Vl = Vh + V_HALF;

            float sacc[8][4];
#pragma unroll
            for (int nf = 0; nf < 8; nf++)
#pragma unroll
                for (int c = 0; c < 4; c++) sacc[nf][c] = 0.f;

#pragma unroll
            for (int pp = 0; pp < 2; pp++) {
                const __nv_bfloat16* Kp = pp ? Kl : Kh;
#pragma unroll
                for (int ks = 0; ks < 8; ks++) {
#pragma unroll
                    for (int nf = 0; nf < 8; nf++) {
                        const __nv_bfloat16* bb = Kp + (nf * 8 + g) * SAK
                                                     + ks * 16 + t * 2;
                        hmma16816(sacc[nf], qa_hi[ks],
                                  *(const uint32_t*)bb, *(const uint32_t*)(bb + 8));
                    }
                }
            }
#pragma unroll
            for (int ks = 0; ks < 8; ks++) {
                uint32_t a[4];
                const __nv_bfloat16* al = Ql + ks * 16;
                a[0] = *(const uint32_t*)&al[(g)     * SAK + t * 2];
                a[1] = *(const uint32_t*)&al[(g + 8) * SAK + t * 2];
                a[2] = *(const uint32_t*)&al[(g)     * SAK + t * 2 + 8];
                a[3] = *(const uint32_t*)&al[(g + 8) * SAK + t * 2 + 8];
#pragma unroll
                for (int nf = 0; nf < 8; nf++) {
                    const __nv_bfloat16* bb = Kh + (nf * 8 + g) * SAK
                                                 + ks * 16 + t * 2;
                    hmma16816(sacc[nf], a,
                              *(const uint32_t*)bb, *(const uint32_t*)(bb + 8));
                }
            }

            if (kt == qt) {
                const int row0 = q0 + wm * 16 + g;
#pragma unroll
                for (int nf = 0; nf < 8; nf++) {
                    int col = kt * 64 + nf * 8 + t * 2;
                    if (col     > row0)     sacc[nf][0] = -INFINITY;
                    if (col + 1 > row0)     sacc[nf][1] = -INFINITY;
                    if (col     > row0 + 8) sacc[nf][2] = -INFINITY;
                    if (col + 1 > row0 + 8) sacc[nf][3] = -INFINITY;
                }
            }

            float mx0 = -INFINITY, mx1 = -INFINITY;
#pragma unroll
            for (int nf = 0; nf < 8; nf++) {
                mx0 = fmaxf(mx0, fmaxf(sacc[nf][0], sacc[nf][1]));
                mx1 = fmaxf(mx1, fmaxf(sacc[nf][2], sacc[nf][3]));
            }
            mx0 = fmaxf(mx0, __shfl_xor_sync(0xffffffffu, mx0, 1));
            mx0 = fmaxf(mx0, __shfl_xor_sync(0xffffffffu, mx0, 2));
            mx1 = fmaxf(mx1, __shfl_xor_sync(0xffffffffu, mx1, 1));
            mx1 = fmaxf(mx1, __shfl_xor_sync(0xffffffffu, mx1, 2));
            float mn0 = fmaxf(m0r, mx0), mn1 = fmaxf(m1r, mx1);
            float al0 = __expf(m0r - mn0), al1 = __expf(m1r - mn1);
            m0r = mn0; m1r = mn1;

            float s0 = 0.f, s1 = 0.f;
            uint32_t ph0[8], ph1[8], pl0[8], pl1[8];
#pragma unroll
            for (int nf = 0; nf < 8; nf++) {
                float p00 = __expf(sacc[nf][0] - mn0);
                float p01 = __expf(sacc[nf][1] - mn0);
                float p10 = __expf(sacc[nf][2] - mn1);
                float p11 = __expf(sacc[nf][3] - mn1);
                s0 += p00 + p01;
                s1 += p10 + p11;
                split2(p00, p01, ph0[nf], pl0[nf]);
                split2(p10, p11, ph1[nf], pl1[nf]);
            }
            s0 += __shfl_xor_sync(0xffffffffu, s0, 1);
            s0 += __shfl_xor_sync(0xffffffffu, s0, 2);
            s1 += __shfl_xor_sync(0xffffffffu, s1, 1);
            s1 += __shfl_xor_sync(0xffffffffu, s1, 2);
            l0r = l0r * al0 + s0;
            l1r = l1r * al1 + s1;

#pragma unroll
            for (int nf = 0; nf < 16; nf++) {
                oacc[nf][0] *= al0; oacc[nf][1] *= al0;
                oacc[nf][2] *= al1; oacc[nf][3] *= al1;
            }

#pragma unroll
            for (int pp = 0; pp < 2; pp++) {
                const __nv_bfloat16* Vp = pp ? Vl : Vh;
#pragma unroll
                for (int kk = 0; kk < 4; kk++) {
                    uint32_t a[4] = { ph0[2 * kk], ph1[2 * kk],
                                      ph0[2 * kk + 1], ph1[2 * kk + 1] };
#pragma unroll
                    for (int nf = 0; nf < 16; nf++) {
                        const __nv_bfloat16* bb = Vp + (nf * 8 + g) * SAV
                                                     + kk * 16 + t * 2;
                        hmma16816(oacc[nf], a,
                                  *(const uint32_t*)bb, *(const uint32_t*)(bb + 8));
                    }
                }
            }
#pragma unroll
            for (int kk = 0; kk < 4; kk++) {
                uint32_t a[4] = { pl0[2 * kk], pl1[2 * kk],
                                  pl0[2 * kk + 1], pl1[2 * kk + 1] };
#pragma unroll
                for (int nf = 0; nf < 16; nf++) {
                    const __nv_bfloat16* bb = Vh + (nf * 8 + g) * SAV
                                                 + kk * 16 + t * 2;
                    hmma16816(oacc[nf], a,
                              *(const uint32_t*)bb, *(const uint32_t*)(bb + 8));
                }
            }
        }
        __syncthreads();
    }

    const float i0 = 1.0f / l0r, i1 = 1.0f / l1r;
    const int row0 = b * T_ + q0 + wm * 16 + g;
#pragma unroll
    for (int nf = 0; nf < 16; nf++) {
        int col = nf * 8 + t * 2;
        *(float2*)&out[(size_t)row0 * HD_ + col] =
            make_float2(oacc[nf][0] * i0, oacc[nf][1] * i0);
        *(float2*)&out[(size_t)(row0 + 8) * HD_ + col] =
            make_float2(oacc[nf][2] * i1, oacc[nf][3] * i1);
    }
}

// ---------------------------------------------------------------------------
extern "C" void kernel_launch(void* const* d_in, const int* in_sizes, int n_in,
                              void* d_out, int out_size)
{
    const float* x  = (const float*)d_in[0];
    const float* Wq = (const float*)d_in[1];
    const float* Wk = (const float*)d_in[2];
    const float* Wv = (const float*)d_in[3];
    float* out = (float*)d_out;
    (void)in_sizes; (void)n_in; (void)out_size;

    cudaFuncSetAttribute(qkv_hmma_kernel,
                         cudaFuncAttributeMaxDynamicSharedMemorySize, QKV_SMEM_B);
    cudaFuncSetAttribute(attn_hmma_kernel,
                         cudaFuncAttributeMaxDynamicSharedMemorySize, ATTN_SMEM_B);

    convert_x_kernel<<<(M_TOT * (NE_ / 4)) / 256, 256>>>(x);
    convert_w_kernel<<<(3 * NE_ * HD_) / 256, 256>>>(Wq, Wk, Wv);
    qkv_hmma_kernel<<<dim3(3, M_TOT / 128), 256, QKV_SMEM_B>>>();
    attn_hmma_kernel<<<dim3(32, B_), 256, ATTN_SMEM_B>>>(out);
}

// round 10
// speedup vs baseline: 3.6978x; 1.0141x over previous
#include <cuda_runtime.h>
#include <cuda_bf16.h>
#include <math.h>
#include <stdint.h>

#define B_  4
#define T_  4096
#define NE_ 2048
#define HD_ 128
#define M_TOT (B_ * T_)

// ---------------------------------------------------------------------------
// Device scratch (no allocations allowed)
// ---------------------------------------------------------------------------
__device__ __nv_bfloat16 g_xhi[(size_t)M_TOT * NE_];
__device__ __nv_bfloat16 g_xlo[(size_t)M_TOT * NE_];
__device__ __nv_bfloat16 g_wt_hi[3 * HD_ * NE_];
__device__ __nv_bfloat16 g_wt_lo[3 * HD_ * NE_];
// projections, bf16 hi/lo. Q pre-scaled by 1/sqrt(128). Vt transposed [B][128][T]
__device__ __nv_bfloat16 g_Qhi[M_TOT * HD_], g_Qlo[M_TOT * HD_];
__device__ __nv_bfloat16 g_Khi[M_TOT * HD_], g_Klo[M_TOT * HD_];
__device__ __nv_bfloat16 g_Vthi[M_TOT * HD_], g_Vtlo[M_TOT * HD_];

// ---------------------------------------------------------------------------
// helpers
// ---------------------------------------------------------------------------
__device__ __forceinline__ void hmma16816(float* c, const uint32_t* a,
                                          uint32_t b0, uint32_t b1)
{
    asm volatile(
        "mma.sync.aligned.m16n8k16.row.col.f32.bf16.bf16.f32 "
        "{%0,%1,%2,%3}, {%4,%5,%6,%7}, {%8,%9}, {%0,%1,%2,%3};"
        : "+f"(c[0]), "+f"(c[1]), "+f"(c[2]), "+f"(c[3])
        : "r"(a[0]), "r"(a[1]), "r"(a[2]), "r"(a[3]), "r"(b0), "r"(b1));
}

__device__ __forceinline__ uint32_t smem_u32(const void* p) {
    uint32_t a;
    asm("{ .reg .u64 t; cvta.to.shared.u64 t, %1; cvt.u32.u64 %0, t; }"
        : "=r"(a) : "l"(p));
    return a;
}

__device__ __forceinline__ void cp_async16(uint32_t dst, const void* src) {
    asm volatile("cp.async.cg.shared.global [%0], [%1], 16;"
                 :: "r"(dst), "l"(src) : "memory");
}

__device__ __forceinline__ void split2(float a, float b, uint32_t& hi, uint32_t& lo) {
    __nv_bfloat162 h = __floats2bfloat162_rn(a, b);
    float ra = a - __low2float(h);
    float rb = b - __high2float(h);
    __nv_bfloat162 l = __floats2bfloat162_rn(ra, rb);
    hi = *(uint32_t*)&h;
    lo = *(uint32_t*)&l;
}

// ---------------------------------------------------------------------------
// Kernel 0a: x -> bf16 hi/lo
// ---------------------------------------------------------------------------
__global__ __launch_bounds__(256) void convert_x_kernel(const float* __restrict__ x)
{
    size_t i = ((size_t)blockIdx.x * 256 + threadIdx.x) * 4;
    float4 v = *(const float4*)(x + i);
    uint32_t h0, l0, h1, l1;
    split2(v.x, v.y, h0, l0);
    split2(v.z, v.w, h1, l1);
    *(uint32_t*)(g_xhi + i)     = h0;
    *(uint32_t*)(g_xhi + i + 2) = h1;
    *(uint32_t*)(g_xlo + i)     = l0;
    *(uint32_t*)(g_xlo + i + 2) = l1;
}

// ---------------------------------------------------------------------------
// Kernel 0b: W -> W^T bf16 hi/lo
// ---------------------------------------------------------------------------
__global__ __launch_bounds__(256) void convert_w_kernel(
    const float* __restrict__ Wq, const float* __restrict__ Wk,
    const float* __restrict__ Wv)
{
    int t = blockIdx.x * 256 + threadIdx.x;
    int o = t / (NE_ * HD_);
    int rem = t - o * (NE_ * HD_);
    int k = rem / HD_;
    int n = rem - k * HD_;
    const float* W = (o == 0) ? Wq : (o == 1) ? Wk : Wv;
    float v = W[(size_t)k * HD_ + n];
    __nv_bfloat16 h = __float2bfloat16(v);
    float lo = v - __bfloat162float(h);
    size_t dst = ((size_t)o * HD_ + n) * NE_ + k;
    g_wt_hi[dst] = h;
    g_wt_lo[dst] = __float2bfloat16(lo);
}

// ---------------------------------------------------------------------------
// Kernel 1: fused QKV projection (HMMA) — unchanged from R7 (passing).
// ---------------------------------------------------------------------------
#define SA 40
#define TILE_ELL (128 * SA)
#define STAGE_ELL (4 * TILE_ELL)
#define QKV_SMEM_B 81920
#define SVT 136

__device__ __forceinline__ void qkv_load_kb(const __nv_bfloat16* Ahi,
                                            const __nv_bfloat16* Alo,
                                            const __nv_bfloat16* Bhi,
                                            const __nv_bfloat16* Blo,
                                            int k0, int st, int tid, uint32_t sbu)
{
    const __nv_bfloat16* srcs[4] = { Ahi, Alo, Bhi, Blo };
#pragma unroll
    for (int i = 0; i < 8; i++) {
        int c = tid + i * 256;
        int arr = c >> 9, idx = c & 511;
        int r = idx >> 2, ch = (idx & 3) * 8;
        const __nv_bfloat16* src = srcs[arr] + (size_t)r * NE_ + k0 + ch;
        uint32_t dst = sbu + (uint32_t)(st * STAGE_ELL + arr * TILE_ELL
                                        + r * SA + ch) * 2;
        cp_async16(dst, src);
    }
    asm volatile("cp.async.commit_group;" ::: "memory");
}

__global__ __launch_bounds__(256, 2) void qkv_hmma_kernel()
{
    extern __shared__ __nv_bfloat16 qs[];
    const uint32_t sbu = smem_u32(qs);

    const int o  = blockIdx.x;
    const int m0 = blockIdx.y * 128;
    const int tid  = threadIdx.x;
    const int wid  = tid >> 5;
    const int lane = tid & 31;
    const int wm = wid >> 1;
    const int wn = wid & 1;
    const int g  = lane >> 2;
    const int t  = lane & 3;

    const __nv_bfloat16* Ahi = g_xhi + (size_t)m0 * NE_;
    const __nv_bfloat16* Alo = g_xlo + (size_t)m0 * NE_;
    const __nv_bfloat16* Bhi = g_wt_hi + (size_t)o * HD_ * NE_;
    const __nv_bfloat16* Blo = g_wt_lo + (size_t)o * HD_ * NE_;

    float acc[2][8][4];
#pragma unroll
    for (int mt = 0; mt < 2; mt++)
#pragma unroll
        for (int nt = 0; nt < 8; nt++)
#pragma unroll
            for (int c = 0; c < 4; c++) acc[mt][nt][c] = 0.f;

    qkv_load_kb(Ahi, Alo, Bhi, Blo, 0, 0, tid, sbu);

#pragma unroll 1
    for (int kb = 0; kb < NE_ / 32; kb++) {
        const int st = kb & 1;
        if (kb < NE_ / 32 - 1) {
            qkv_load_kb(Ahi, Alo, Bhi, Blo, (kb + 1) * 32, st ^ 1, tid, sbu);
            asm volatile("cp.async.wait_group 1;" ::: "memory");
        } else {
            asm volatile("cp.async.wait_group 0;" ::: "memory");
        }
        __syncthreads();

        const __nv_bfloat16* sAh = qs + st * STAGE_ELL;
        const __nv_bfloat16* sAl = sAh + TILE_ELL;
        const __nv_bfloat16* sBh = sAh + 2 * TILE_ELL;
        const __nv_bfloat16* sBl = sAh + 3 * TILE_ELL;

#pragma unroll
        for (int ks = 0; ks < 2; ks++) {
            uint32_t a[2][4];
#pragma unroll
            for (int mt = 0; mt < 2; mt++) {
                const __nv_bfloat16* ab = sAh + (wm * 32 + mt * 16) * SA + ks * 16;
                a[mt][0] = *(const uint32_t*)&ab[(g)     * SA + t * 2];
                a[mt][1] = *(const uint32_t*)&ab[(g + 8) * SA + t * 2];
                a[mt][2] = *(const uint32_t*)&ab[(g)     * SA + t * 2 + 8];
                a[mt][3] = *(const uint32_t*)&ab[(g + 8) * SA + t * 2 + 8];
            }
#pragma unroll
            for (int nt = 0; nt < 8; nt++) {
                const __nv_bfloat16* bb = sBh + (wn * 64 + nt * 8 + g) * SA + ks * 16;
                uint32_t b0 = *(const uint32_t*)&bb[t * 2];
                uint32_t b1 = *(const uint32_t*)&bb[t * 2 + 8];
                hmma16816(acc[0][nt], a[0], b0, b1);
                hmma16816(acc[1][nt], a[1], b0, b1);
            }
#pragma unroll
            for (int nt = 0; nt < 8; nt++) {
                const __nv_bfloat16* bb = sBl + (wn * 64 + nt * 8 + g) * SA + ks * 16;
                uint32_t b0 = *(const uint32_t*)&bb[t * 2];
                uint32_t b1 = *(const uint32_t*)&bb[t * 2 + 8];
                hmma16816(acc[0][nt], a[0], b0, b1);
                hmma16816(acc[1][nt], a[1], b0, b1);
            }
#pragma unroll
            for (int mt = 0; mt < 2; mt++) {
                const __nv_bfloat16* ab = sAl + (wm * 32 + mt * 16) * SA + ks * 16;
                a[mt][0] = *(const uint32_t*)&ab[(g)     * SA + t * 2];
                a[mt][1] = *(const uint32_t*)&ab[(g + 8) * SA + t * 2];
                a[mt][2] = *(const uint32_t*)&ab[(g)     * SA + t * 2 + 8];
                a[mt][3] = *(const uint32_t*)&ab[(g + 8) * SA + t * 2 + 8];
            }
#pragma unroll
            for (int nt = 0; nt < 8; nt++) {
                const __nv_bfloat16* bb = sBh + (wn * 64 + nt * 8 + g) * SA + ks * 16;
                uint32_t b0 = *(const uint32_t*)&bb[t * 2];
                uint32_t b1 = *(const uint32_t*)&bb[t * 2 + 8];
                hmma16816(acc[0][nt], a[0], b0, b1);
                hmma16816(acc[1][nt], a[1], b0, b1);
            }
        }
        __syncthreads();
    }

    if (o < 2) {
        __nv_bfloat16* Hh = (o == 0) ? g_Qhi : g_Khi;
        __nv_bfloat16* Hl = (o == 0) ? g_Qlo : g_Klo;
        const float sc = (o == 0) ? 0.08838834764831845f : 1.0f;
#pragma unroll
        for (int mt = 0; mt < 2; mt++) {
            int row = m0 + wm * 32 + mt * 16 + g;
#pragma unroll
            for (int nt = 0; nt < 8; nt++) {
                int col = wn * 64 + nt * 8 + t * 2;
                uint32_t h0, l0, h1, l1;
                split2(acc[mt][nt][0] * sc, acc[mt][nt][1] * sc, h0, l0);
                split2(acc[mt][nt][2] * sc, acc[mt][nt][3] * sc, h1, l1);
                *(uint32_t*)&Hh[(size_t)row * HD_ + col] = h0;
                *(uint32_t*)&Hl[(size_t)row * HD_ + col] = l0;
                *(uint32_t*)&Hh[(size_t)(row + 8) * HD_ + col] = h1;
                *(uint32_t*)&Hl[(size_t)(row + 8) * HD_ + col] = l1;
            }
        }
    } else {
        float* sT = (float*)qs;
#pragma unroll
        for (int mt = 0; mt < 2; mt++) {
            int row = wm * 32 + mt * 16 + g;
#pragma unroll
            for (int nt = 0; nt < 8; nt++) {
                int col = wn * 64 + nt * 8 + t * 2;
                sT[(col)     * SVT + row]     = acc[mt][nt][0];
                sT[(col + 1) * SVT + row]     = acc[mt][nt][1];
                sT[(col)     * SVT + row + 8] = acc[mt][nt][2];
                sT[(col + 1) * SVT + row + 8] = acc[mt][nt][3];
            }
        }
        __syncthreads();
        const int bidx = m0 >> 12;
        const int tok0 = m0 & (T_ - 1);
#pragma unroll
        for (int i = 0; i < 8; i++) {
            int c = tid + i * 256;
            int hd = c >> 4, ch = (c & 15) * 8;
            const float* srcr = sT + hd * SVT + ch;
            uint32_t h[4], l[4];
#pragma unroll
            for (int q = 0; q < 4; q++)
                split2(srcr[q * 2], srcr[q * 2 + 1], h[q], l[q]);
            size_t base = ((size_t)bidx * HD_ + hd) * T_ + tok0 + ch;
            *(uint4*)(g_Vthi + base) = make_uint4(h[0], h[1], h[2], h[3]);
            *(uint4*)(g_Vtlo + base) = make_uint4(l[0], l[1], l[2], l[3]);
        }
    }
}

// ---------------------------------------------------------------------------
// Kernel 2: causal flash attention, HMMA, sequential-fold scheduling.
// CTA = 256 thr = 8 warps (4 m-warps x 2 n-warps) all cooperating on ONE
// 64-row q-tile; each CTA processes q-tile p then 63-p => 65 iters, balanced.
// Cross-warp softmax via smem reduction; P staged via smem bf16 hi/lo.
// ---------------------------------------------------------------------------
#define SAK 136
#define SAV 72
#define SAP 72
#define AQ_HI 0
#define AQ_LO 8704                       // 64*136
#define A_PH  17408                      // P hi: 64*72
#define A_PL  22016
#define A_MRED 26624                     // 128 floats (256 halves)
#define A_LRED 26880                     // 128 floats
#define A_KOFF 27648
#define A_KSTG 17408                     // 2(hi/lo)*64*136
#define A_VOFF (A_KOFF + 2 * A_KSTG)     // 62464
#define A_VHALF 9216                     // 128*72
#define A_VSTG (2 * A_VHALF)             // 18432
#define A_END (A_VOFF + 2 * A_VSTG)      // 99328 halves
#define ATTN_SMEM_B (A_END * 2)          // 198656 B

__device__ __forceinline__ void load_kv_tile(int b, int kt, int st, int tid,
                                             uint32_t sbu)
{
#pragma unroll
    for (int i = 0; i < 8; i++) {
        int c = tid + i * 256;
        int arr = c >> 10, idx = c & 1023;
        int r = idx >> 4, ch = (idx & 15) * 8;
        const __nv_bfloat16* src = (arr ? g_Klo : g_Khi)
            + ((size_t)(b * T_ + kt * 64 + r)) * HD_ + ch;
        uint32_t dst = sbu + (uint32_t)(A_KOFF + st * A_KSTG + arr * (64 * SAK)
                                        + r * SAK + ch) * 2;
        cp_async16(dst, src);
    }
#pragma unroll
    for (int i = 0; i < 8; i++) {
        int c = tid + i * 256;
        int arr = c >> 10, idx = c & 1023;
        int hd = idx >> 3, ch = (idx & 7) * 8;
        const __nv_bfloat16* src = (arr ? g_Vtlo : g_Vthi)
            + ((size_t)b * HD_ + hd) * T_ + kt * 64 + ch;
        uint32_t dst = sbu + (uint32_t)(A_VOFF + st * A_VSTG + arr * A_VHALF
                                        + hd * SAV + ch) * 2;
        cp_async16(dst, src);
    }
    asm volatile("cp.async.commit_group;" ::: "memory");
}

__global__ __launch_bounds__(256, 1) void attn_hmma_kernel(float* __restrict__ out)
{
    extern __shared__ __nv_bfloat16 sb[];
    const uint32_t sbu = smem_u32(sb);
    const int b   = blockIdx.y;
    const int p   = blockIdx.x;          // 0..31
    const int tid = threadIdx.x;
    const int wid = tid >> 5, lane = tid & 31;
    const int g   = lane >> 2, t = lane & 3;
    const int wm  = wid & 3, wn = wid >> 2;
    float* mred = (float*)(sb + A_MRED);
    float* lred = (float*)(sb + A_LRED);

    int stg = 0;    // next stage to load into

#pragma unroll 1
    for (int ph = 0; ph < 2; ph++) {
        const int qt = ph ? (63 - p) : p;
        const int q0 = qt * 64;
        const int n  = qt + 1;

        // load Q tile hi/lo (64 rows x 128 cols)
#pragma unroll
        for (int i = 0; i < 8; i++) {
            int c = tid + i * 256;
            int arr = c >> 10, idx = c & 1023;
            int r = idx >> 4, c8 = (idx & 15) * 8;
            const __nv_bfloat16* src = (arr ? g_Qlo : g_Qhi)
                + ((size_t)(b * T_ + q0 + r)) * HD_ + c8;
            *(uint4*)&sb[(arr ? AQ_LO : AQ_HI) + r * SAK + c8] = *(const uint4*)src;
        }
        // prefetch kv tile 0 of this phase
        load_kv_tile(b, 0, stg, tid, sbu);
        int cur = stg; stg ^= 1;
        __syncthreads();

        // hoist Q-hi a-frags (rows wm*16 + g, +8)
        uint32_t qa_hi[8][4];
        const __nv_bfloat16* Qh = sb + AQ_HI + wm * 16 * SAK;
        const __nv_bfloat16* Ql = sb + AQ_LO + wm * 16 * SAK;
#pragma unroll
        for (int ks = 0; ks < 8; ks++) {
            const __nv_bfloat16* ah = Qh + ks * 16;
            qa_hi[ks][0] = *(const uint32_t*)&ah[(g)     * SAK + t * 2];
            qa_hi[ks][1] = *(const uint32_t*)&ah[(g + 8) * SAK + t * 2];
            qa_hi[ks][2] = *(const uint32_t*)&ah[(g)     * SAK + t * 2 + 8];
            qa_hi[ks][3] = *(const uint32_t*)&ah[(g + 8) * SAK + t * 2 + 8];
        }

        float m0r = -INFINITY, m1r = -INFINITY, l0r = 0.f, l1r = 0.f;
        float oacc[8][4];
#pragma unroll
        for (int nf = 0; nf < 8; nf++)
#pragma unroll
            for (int c = 0; c < 4; c++) oacc[nf][c] = 0.f;

        const int row0 = wm * 16 + g;     // local row (0..63)

#pragma unroll 1
        for (int kt = 0; kt < n; kt++) {
            if (kt + 1 < n) {
                load_kv_tile(b, kt + 1, stg, tid, sbu);
                stg ^= 1;
                asm volatile("cp.async.wait_group 1;" ::: "memory");
            } else {
                asm volatile("cp.async.wait_group 0;" ::: "memory");
            }
            __syncthreads();                                  // sync1

            const __nv_bfloat16* Kh = sb + A_KOFF + cur * A_KSTG;
            const __nv_bfloat16* Kl = Kh + 64 * SAK;
            const __nv_bfloat16* Vh = sb + A_VOFF + cur * A_VSTG;
            const __nv_bfloat16* Vl = Vh + A_VHALF;

            // ---- S (this warp: rows wm*16.., cols wn*32 + nf*8) ----
            float sacc[4][4];
#pragma unroll
            for (int nf = 0; nf < 4; nf++)
#pragma unroll
                for (int c = 0; c < 4; c++) sacc[nf][c] = 0.f;

#pragma unroll
            for (int pp = 0; pp < 2; pp++) {
                const __nv_bfloat16* Kp = pp ? Kl : Kh;
#pragma unroll
                for (int ks = 0; ks < 8; ks++) {
#pragma unroll
                    for (int nf = 0; nf < 4; nf++) {
                        const __nv_bfloat16* bb = Kp + (wn * 32 + nf * 8 + g) * SAK
                                                     + ks * 16 + t * 2;
                        hmma16816(sacc[nf], qa_hi[ks],
                                  *(const uint32_t*)bb, *(const uint32_t*)(bb + 8));
                    }
                }
            }
#pragma unroll
            for (int ks = 0; ks < 8; ks++) {
                uint32_t a[4];
                const __nv_bfloat16* al = Ql + ks * 16;
                a[0] = *(const uint32_t*)&al[(g)     * SAK + t * 2];
                a[1] = *(const uint32_t*)&al[(g + 8) * SAK + t * 2];
                a[2] = *(const uint32_t*)&al[(g)     * SAK + t * 2 + 8];
                a[3] = *(const uint32_t*)&al[(g + 8) * SAK + t * 2 + 8];
#pragma unroll
                for (int nf = 0; nf < 4; nf++) {
                    const __nv_bfloat16* bb = Kh + (wn * 32 + nf * 8 + g) * SAK
                                                 + ks * 16 + t * 2;
                    hmma16816(sacc[nf], a,
                              *(const uint32_t*)bb, *(const uint32_t*)(bb + 8));
                }
            }

            // ---- causal mask (diagonal tile) ----
            if (kt == qt) {
                const int gr = q0 + row0;
#pragma unroll
                for (int nf = 0; nf < 4; nf++) {
                    int col = kt * 64 + wn * 32 + nf * 8 + t * 2;
                    if (col     > gr)     sacc[nf][0] = -INFINITY;
                    if (col + 1 > gr)     sacc[nf][1] = -INFINITY;
                    if (col     > gr + 8) sacc[nf][2] = -INFINITY;
                    if (col + 1 > gr + 8) sacc[nf][3] = -INFINITY;
                }
            }

            // ---- softmax: warp-local max, cross-wn combine via smem ----
            float mx0 = -INFINITY, mx1 = -INFINITY;
#pragma unroll
            for (int nf = 0; nf < 4; nf++) {
                mx0 = fmaxf(mx0, fmaxf(sacc[nf][0], sacc[nf][1]));
                mx1 = fmaxf(mx1, fmaxf(sacc[nf][2], sacc[nf][3]));
            }
            mx0 = fmaxf(mx0, __shfl_xor_sync(0xffffffffu, mx0, 1));
            mx0 = fmaxf(mx0, __shfl_xor_sync(0xffffffffu, mx0, 2));
            mx1 = fmaxf(mx1, __shfl_xor_sync(0xffffffffu, mx1, 1));
            mx1 = fmaxf(mx1, __shfl_xor_sync(0xffffffffu, mx1, 2));
            if (t == 0) {
                mred[wn * 64 + row0]     = mx0;
                mred[wn * 64 + row0 + 8] = mx1;
            }
            __syncthreads();                                  // sync2
            float mn0 = fmaxf(m0r, fmaxf(mx0, mred[(wn ^ 1) * 64 + row0]));
            float mn1 = fmaxf(m1r, fmaxf(mx1, mred[(wn ^ 1) * 64 + row0 + 8]));
            float al0 = __expf(m0r - mn0), al1 = __expf(m1r - mn1);
            m0r = mn0; m1r = mn1;

            float s0 = 0.f, s1 = 0.f;
#pragma unroll
            for (int nf = 0; nf < 4; nf++) {
                float p00 = __expf(sacc[nf][0] - mn0);
                float p01 = __expf(sacc[nf][1] - mn0);
                float p10 = __expf(sacc[nf][2] - mn1);
                float p11 = __expf(sacc[nf][3] - mn1);
                s0 += p00 + p01;
                s1 += p10 + p11;
                uint32_t h0, l0, h1, l1;
                split2(p00, p01, h0, l0);
                split2(p10, p11, h1, l1);
                int colh = wn * 32 + nf * 8 + t * 2;
                *(uint32_t*)&sb[A_PH + (row0)     * SAP + colh] = h0;
                *(uint32_t*)&sb[A_PL + (row0)     * SAP + colh] = l0;
                *(uint32_t*)&sb[A_PH + (row0 + 8) * SAP + colh] = h1;
                *(uint32_t*)&sb[A_PL + (row0 + 8) * SAP + colh] = l1;
            }
            s0 += __shfl_xor_sync(0xffffffffu, s0, 1);
            s0 += __shfl_xor_sync(0xffffffffu, s0, 2);
            s1 += __shfl_xor_sync(0xffffffffu, s1, 1);
            s1 += __shfl_xor_sync(0xffffffffu, s1, 2);
            if (t == 0) {
                lred[wn * 64 + row0]     = s0;
                lred[wn * 64 + row0 + 8] = s1;
            }
            __syncthreads();                                  // sync3 (P + lred)
            l0r = l0r * al0 + s0 + lred[(wn ^ 1) * 64 + row0];
            l1r = l1r * al1 + s1 + lred[(wn ^ 1) * 64 + row0 + 8];

#pragma unroll
            for (int nf = 0; nf < 8; nf++) {
                oacc[nf][0] *= al0; oacc[nf][1] *= al0;
                oacc[nf][2] *= al1; oacc[nf][3] *= al1;
            }

            // ---- O += Phi*Vhi + Phi*Vlo + Plo*Vhi ----
            const __nv_bfloat16* Ph = sb + A_PH;
            const __nv_bfloat16* Pl = sb + A_PL;
#pragma unroll
            for (int pass = 0; pass < 3; pass++) {
                const __nv_bfloat16* Ap = (pass == 2) ? Pl : Ph;
                const __nv_bfloat16* Vp = (pass == 1) ? Vl : Vh;
#pragma unroll
                for (int kk = 0; kk < 4; kk++) {
                    uint32_t a[4];
                    const __nv_bfloat16* ab = Ap + kk * 16;
                    a[0] = *(const uint32_t*)&ab[(row0)     * SAP + t * 2];
                    a[1] = *(const uint32_t*)&ab[(row0 + 8) * SAP + t * 2];
                    a[2] = *(const uint32_t*)&ab[(row0)     * SAP + t * 2 + 8];
                    a[3] = *(const uint32_t*)&ab[(row0 + 8) * SAP + t * 2 + 8];
#pragma unroll
                    for (int nf = 0; nf < 8; nf++) {
                        const __nv_bfloat16* bb = Vp + (wn * 64 + nf * 8 + g) * SAV
                                                     + kk * 16 + t * 2;
                        hmma16816(oacc[nf], a,
                                  *(const uint32_t*)bb, *(const uint32_t*)(bb + 8));
                    }
                }
            }
            cur ^= (kt + 1 < n) ? 1 : 0;
            __syncthreads();                                  // sync4
        }

        // ---- epilogue for this q-tile ----
        const float i0 = 1.0f / l0r, i1 = 1.0f / l1r;
        const int grow = b * T_ + q0 + row0;
#pragma unroll
        for (int nf = 0; nf < 8; nf++) {
            int col = wn * 64 + nf * 8 + t * 2;
            *(float2*)&out[(size_t)grow * HD_ + col] =
                make_float2(oacc[nf][0] * i0, oacc[nf][1] * i0);
            *(float2*)&out[(size_t)(grow + 8) * HD_ + col] =
                make_float2(oacc[nf][2] * i1, oacc[nf][3] * i1);
        }
    }
}

// ---------------------------------------------------------------------------
extern "C" void kernel_launch(void* const* d_in, const int* in_sizes, int n_in,
                              void* d_out, int out_size)
{
    const float* x  = (const float*)d_in[0];
    const float* Wq = (const float*)d_in[1];
    const float* Wk = (const float*)d_in[2];
    const float* Wv = (const float*)d_in[3];
    float* out = (float*)d_out;
    (void)in_sizes; (void)n_in; (void)out_size;

    cudaFuncSetAttribute(qkv_hmma_kernel,
                         cudaFuncAttributeMaxDynamicSharedMemorySize, QKV_SMEM_B);
    cudaFuncSetAttribute(attn_hmma_kernel,
                         cudaFuncAttributeMaxDynamicSharedMemorySize, ATTN_SMEM_B);

    convert_x_kernel<<<(M_TOT * (NE_ / 4)) / 256, 256>>>(x);
    convert_w_kernel<<<(3 * NE_ * HD_) / 256, 256>>>(Wq, Wk, Wv);
    qkv_hmma_kernel<<<dim3(3, M_TOT / 128), 256, QKV_SMEM_B>>>();
    attn_hmma_kernel<<<dim3(32, B_), 256, ATTN_SMEM_B>>>(out);
}

// round 12
// speedup vs baseline: 3.7557x; 1.0157x over previous
#include <cuda_runtime.h>
#include <cuda_bf16.h>
#include <math.h>
#include <stdint.h>

#define B_  4
#define T_  4096
#define NE_ 2048
#define HD_ 128
#define M_TOT (B_ * T_)

// ---------------------------------------------------------------------------
// Device scratch (no allocations allowed)
// ---------------------------------------------------------------------------
__device__ __nv_bfloat16 g_wt_hi[3 * HD_ * NE_];
__device__ __nv_bfloat16 g_wt_lo[3 * HD_ * NE_];
// projections, bf16 hi/lo. Q pre-scaled by 1/sqrt(128). Vt transposed [B][128][T]
__device__ __nv_bfloat16 g_Qhi[M_TOT * HD_], g_Qlo[M_TOT * HD_];
__device__ __nv_bfloat16 g_Khi[M_TOT * HD_], g_Klo[M_TOT * HD_];
__device__ __nv_bfloat16 g_Vthi[M_TOT * HD_], g_Vtlo[M_TOT * HD_];

// ---------------------------------------------------------------------------
// helpers
// ---------------------------------------------------------------------------
__device__ __forceinline__ void hmma16816(float* c, const uint32_t* a,
                                          uint32_t b0, uint32_t b1)
{
    asm volatile(
        "mma.sync.aligned.m16n8k16.row.col.f32.bf16.bf16.f32 "
        "{%0,%1,%2,%3}, {%4,%5,%6,%7}, {%8,%9}, {%0,%1,%2,%3};"
        : "+f"(c[0]), "+f"(c[1]), "+f"(c[2]), "+f"(c[3])
        : "r"(a[0]), "r"(a[1]), "r"(a[2]), "r"(a[3]), "r"(b0), "r"(b1));
}

__device__ __forceinline__ void ldsm_x4(uint32_t& r0, uint32_t& r1,
                                        uint32_t& r2, uint32_t& r3, uint32_t addr)
{
    asm volatile("ldmatrix.sync.aligned.m8n8.x4.shared.b16 {%0,%1,%2,%3}, [%4];"
                 : "=r"(r0), "=r"(r1), "=r"(r2), "=r"(r3) : "r"(addr));
}

__device__ __forceinline__ uint32_t smem_u32(const void* p) {
    uint32_t a;
    asm("{ .reg .u64 t; cvta.to.shared.u64 t, %1; cvt.u32.u64 %0, t; }"
        : "=r"(a) : "l"(p));
    return a;
}

__device__ __forceinline__ void cp_async16(uint32_t dst, const void* src) {
    asm volatile("cp.async.cg.shared.global [%0], [%1], 16;"
                 :: "r"(dst), "l"(src) : "memory");
}

__device__ __forceinline__ void split2(float a, float b, uint32_t& hi, uint32_t& lo) {
    __nv_bfloat162 h = __floats2bfloat162_rn(a, b);
    float ra = a - __low2float(h);
    float rb = b - __high2float(h);
    __nv_bfloat162 l = __floats2bfloat162_rn(ra, rb);
    hi = *(uint32_t*)&h;
    lo = *(uint32_t*)&l;
}

// ---------------------------------------------------------------------------
// Kernel 0: W -> W^T bf16 hi/lo
// ---------------------------------------------------------------------------
__global__ __launch_bounds__(256) void convert_w_kernel(
    const float* __restrict__ Wq, const float* __restrict__ Wk,
    const float* __restrict__ Wv)
{
    int t = blockIdx.x * 256 + threadIdx.x;
    int o = t / (NE_ * HD_);
    int rem = t - o * (NE_ * HD_);
    int k = rem / HD_;
    int n = rem - k * HD_;
    const float* W = (o == 0) ? Wq : (o == 1) ? Wk : Wv;
    float v = W[(size_t)k * HD_ + n];
    __nv_bfloat16 h = __float2bfloat16(v);
    float lo = v - __bfloat162float(h);
    size_t dst = ((size_t)o * HD_ + n) * NE_ + k;
    g_wt_hi[dst] = h;
    g_wt_lo[dst] = __float2bfloat16(lo);
}

// ---------------------------------------------------------------------------
// Kernel 1: fused QKV projection. Reads x fp32 ONCE, converts to bf16 hi/lo
// in-kernel, computes Q,K,V together. grid (2, 128): bx = 64-col half,
// by = 128-row M tile. 256 thr = 4m x 2n warps; warp slab = 32 rows x 96 cols
// of the 192-col (3 outputs x 64) slab. cp.async double-buffered.
// ---------------------------------------------------------------------------
#define QSA 40                    // bf16 tile k-stride (halves)
#define QAF_B 0                   // fp32 A tile: 128 x 36 floats (144B rows)
#define QAH_B 18432
#define QAL_B 28672
#define QB_B  38912               // 6 bf16 B tiles (o x {hi,lo}) of 5120 B
#define QSTG_B 69632
#define QKV_SMEM_B (2 * QSTG_B)   // 139264

__device__ __forceinline__ void qkv_issue(const float* __restrict__ x,
                                          int bx, int m0, int k0,
                                          uint32_t sb_st, int tid)
{
#pragma unroll
    for (int i = 0; i < 4; i++) {            // A fp32: 1024 x 16B
        int c = tid + i * 256;
        int r = c >> 3, q = c & 7;
        cp_async16(sb_st + QAF_B + (uint32_t)(r * 144 + q * 16),
                   x + (size_t)(m0 + r) * NE_ + k0 + q * 4);
    }
#pragma unroll
    for (int i = 0; i < 6; i++) {            // B: 6 tiles x 256 x 16B
        int c = tid + i * 256;
        int tl = c >> 8, idx = c & 255;
        int r = idx >> 2, q = idx & 3;
        int o = tl >> 1, wh = tl & 1;
        const __nv_bfloat16* src = (wh ? g_wt_lo : g_wt_hi)
            + (size_t)(o * HD_ + bx * 64 + r) * NE_ + k0 + q * 8;
        cp_async16(sb_st + QB_B + (uint32_t)(tl * 5120 + r * 80 + q * 16), src);
    }
    asm volatile("cp.async.commit_group;" ::: "memory");
}

__global__ __launch_bounds__(256) void qkv_hmma_kernel(const float* __restrict__ x)
{
    extern __shared__ char qsm[];
    const uint32_t sbu = smem_u32(qsm);
    const int bx = blockIdx.x;
    const int m0 = blockIdx.y * 128;
    const int tid = threadIdx.x;
    const int wid = tid >> 5, lane = tid & 31;
    const int wm = wid >> 1, wn = wid & 1;
    const int g = lane >> 2, t = lane & 3;

    // ldmatrix lane offsets (halves), stride QSA
    const uint32_t b40 = (uint32_t)(((((lane >> 4) & 1) << 3) + (lane & 7)) * QSA
                                    + (((lane >> 3) & 1) << 3));
    const uint32_t a40 = (uint32_t)(((((lane >> 3) & 1) << 3) + (lane & 7)) * QSA
                                    + (((lane >> 4) & 1) << 3));

    float acc[2][12][4];
#pragma unroll
    for (int mt = 0; mt < 2; mt++)
#pragma unroll
        for (int nt = 0; nt < 12; nt++)
#pragma unroll
            for (int c = 0; c < 4; c++) acc[mt][nt][c] = 0.f;

    qkv_issue(x, bx, m0, 0, sbu, tid);

#pragma unroll 1
    for (int kb = 0; kb < NE_ / 32; kb++) {
        const int st = kb & 1;
        const uint32_t sb_st = sbu + st * QSTG_B;
        if (kb < NE_ / 32 - 1) {
            qkv_issue(x, bx, m0, (kb + 1) * 32, sbu + (st ^ 1) * QSTG_B, tid);
            asm volatile("cp.async.wait_group 1;" ::: "memory");
        } else {
            asm volatile("cp.async.wait_group 0;" ::: "memory");
        }
        __syncthreads();

        // convert AF fp32 -> AH/AL bf16 (2048 float-pairs)
#pragma unroll
        for (int i = 0; i < 8; i++) {
            int pidx = tid + i * 256;
            int r = pidx >> 4, pc = (pidx & 15) * 2;
            float2 v = *(const float2*)(qsm + st * QSTG_B + QAF_B + r * 144 + pc * 4);
            uint32_t h, l;
            split2(v.x, v.y, h, l);
            *(uint32_t*)(qsm + st * QSTG_B + QAH_B + r * 80 + pc * 2) = h;
            *(uint32_t*)(qsm + st * QSTG_B + QAL_B + r * 80 + pc * 2) = l;
        }
        __syncthreads();

#pragma unroll
        for (int ks = 0; ks < 2; ks++) {
            uint32_t a[2][4];
#pragma unroll
            for (int mt = 0; mt < 2; mt++)
                ldsm_x4(a[mt][0], a[mt][1], a[mt][2], a[mt][3],
                        sb_st + QAH_B
                        + 2 * (uint32_t)((wm * 32 + mt * 16) * QSA + ks * 16 + a40));
            // passes 0 (Ahi*Bhi) and 1 (Ahi*Blo)
#pragma unroll
            for (int wh = 0; wh < 2; wh++) {
#pragma unroll
                for (int n2 = 0; n2 < 6; n2++) {
                    int col = wn * 96 + n2 * 16;
                    int o = col >> 6, rn = col & 63;
                    uint32_t b0, b1, b2, b3;
                    ldsm_x4(b0, b1, b2, b3,
                            sb_st + QB_B + (uint32_t)((o * 2 + wh) * 5120)
                            + 2 * (uint32_t)(rn * QSA + ks * 16 + b40));
                    hmma16816(acc[0][n2 * 2],     a[0], b0, b1);
                    hmma16816(acc[1][n2 * 2],     a[1], b0, b1);
                    hmma16816(acc[0][n2 * 2 + 1], a[0], b2, b3);
                    hmma16816(acc[1][n2 * 2 + 1], a[1], b2, b3);
                }
            }
            // pass 2: Alo * Bhi
#pragma unroll
            for (int mt = 0; mt < 2; mt++)
                ldsm_x4(a[mt][0], a[mt][1], a[mt][2], a[mt][3],
                        sb_st + QAL_B
                        + 2 * (uint32_t)((wm * 32 + mt * 16) * QSA + ks * 16 + a40));
#pragma unroll
            for (int n2 = 0; n2 < 6; n2++) {
                int col = wn * 96 + n2 * 16;
                int o = col >> 6, rn = col & 63;
                uint32_t b0, b1, b2, b3;
                ldsm_x4(b0, b1, b2, b3,
                        sb_st + QB_B + (uint32_t)(o * 2 * 5120)
                        + 2 * (uint32_t)(rn * QSA + ks * 16 + b40));
                hmma16816(acc[0][n2 * 2],     a[0], b0, b1);
                hmma16816(acc[1][n2 * 2],     a[1], b0, b1);
                hmma16816(acc[0][n2 * 2 + 1], a[0], b2, b3);
                hmma16816(acc[1][n2 * 2 + 1], a[1], b2, b3);
            }
        }
        __syncthreads();
    }

    // ---- epilogue: Q/K direct hi/lo; V via smem transpose ----
    const int bidx = m0 >> 12;
    const int tok0 = m0 & (T_ - 1);
#pragma unroll
    for (int mt = 0; mt < 2; mt++) {
#pragma unroll
        for (int nt = 0; nt < 12; nt++) {
            int col192 = wn * 96 + nt * 8;
            int o = col192 >> 6, c64 = col192 & 63;
            if (o < 2) {
                __nv_bfloat16* Hh = o ? g_Khi : g_Qhi;
                __nv_bfloat16* Hl = o ? g_Klo : g_Qlo;
                float sc = o ? 1.0f : 0.08838834764831845f;
                int row = m0 + wm * 32 + mt * 16 + g;
                int colg = bx * 64 + c64 + t * 2;
                uint32_t h0, l0, h1, l1;
                split2(acc[mt][nt][0] * sc, acc[mt][nt][1] * sc, h0, l0);
                split2(acc[mt][nt][2] * sc, acc[mt][nt][3] * sc, h1, l1);
                *(uint32_t*)&Hh[(size_t)row * HD_ + colg] = h0;
                *(uint32_t*)&Hl[(size_t)row * HD_ + colg] = l0;
                *(uint32_t*)&Hh[(size_t)(row + 8) * HD_ + colg] = h1;
                *(uint32_t*)&Hl[(size_t)(row + 8) * HD_ + colg] = l1;
            }
        }
    }
    float* sT = (float*)qsm;      // [64 hd][132 rows] fp32 = 33792 B
    if (wn == 1) {
#pragma unroll
        for (int mt = 0; mt < 2; mt++) {
            int row = wm * 32 + mt * 16 + g;
#pragma unroll
            for (int nt = 4; nt < 12; nt++) {
                int col = nt * 8 - 32 + t * 2;
                sT[(col)     * 132 + row]     = acc[mt][nt][0];
                sT[(col + 1) * 132 + row]     = acc[mt][nt][1];
                sT[(col)     * 132 + row + 8] = acc[mt][nt][2];
                sT[(col + 1) * 132 + row + 8] = acc[mt][nt][3];
            }
        }
    }
    __syncthreads();
#pragma unroll
    for (int i = 0; i < 4; i++) {
        int c = tid + i * 256;
        int hd = c >> 4, tk = (c & 15) * 8;
        const float* sr = sT + hd * 132 + tk;
        uint32_t h[4], l[4];
#pragma unroll
        for (int q = 0; q < 4; q++) split2(sr[2 * q], sr[2 * q + 1], h[q], l[q]);
        size_t base = ((size_t)bidx * HD_ + bx * 64 + hd) * T_ + tok0 + tk;
        *(uint4*)(g_Vthi + base) = make_uint4(h[0], h[1], h[2], h[3]);
        *(uint4*)(g_Vtlo + base) = make_uint4(l[0], l[1], l[2], l[3]);
    }
}

// ---------------------------------------------------------------------------
// Kernel 2: causal flash attention, HMMA, sequential-fold, ldmatrix loads.
// ---------------------------------------------------------------------------
#define SAK 136
#define SAV 72
#define SAP 72
#define AQ_HI 0
#define AQ_LO 8704
#define A_PH  17408
#define A_PL  22016
#define A_MRED 26624
#define A_LRED 26880
#define A_KOFF 27648
#define A_KSTG 17408
#define A_VOFF (A_KOFF + 2 * A_KSTG)
#define A_VHALF 9216
#define A_VSTG (2 * A_VHALF)
#define A_END (A_VOFF + 2 * A_VSTG)
#define ATTN_SMEM_B (A_END * 2)

__device__ __forceinline__ void load_kv_tile(int b, int kt, int st, int tid,
                                             uint32_t sbu)
{
#pragma unroll
    for (int i = 0; i < 8; i++) {
        int c = tid + i * 256;
        int arr = c >> 10, idx = c & 1023;
        int r = idx >> 4, ch = (idx & 15) * 8;
        const __nv_bfloat16* src = (arr ? g_Klo : g_Khi)
            + ((size_t)(b * T_ + kt * 64 + r)) * HD_ + ch;
        uint32_t dst = sbu + (uint32_t)(A_KOFF + st * A_KSTG + arr * (64 * SAK)
                                        + r * SAK + ch) * 2;
        cp_async16(dst, src);
    }
#pragma unroll
    for (int i = 0; i < 8; i++) {
        int c = tid + i * 256;
        int arr = c >> 10, idx = c & 1023;
        int hd = idx >> 3, ch = (idx & 7) * 8;
        const __nv_bfloat16* src = (arr ? g_Vtlo : g_Vthi)
            + ((size_t)b * HD_ + hd) * T_ + kt * 64 + ch;
        uint32_t dst = sbu + (uint32_t)(A_VOFF + st * A_VSTG + arr * A_VHALF
                                        + hd * SAV + ch) * 2;
        cp_async16(dst, src);
    }
    asm volatile("cp.async.commit_group;" ::: "memory");
}

__global__ __launch_bounds__(256, 1) void attn_hmma_kernel(float* __restrict__ out)
{
    extern __shared__ __nv_bfloat16 sb[];
    const uint32_t sbu = smem_u32(sb);
    const int b   = blockIdx.y;
    const int p   = blockIdx.x;
    const int tid = threadIdx.x;
    const int wid = tid >> 5, lane = tid & 31;
    const int g   = lane >> 2, t = lane & 3;
    const int wm  = wid & 3, wn = wid >> 2;
    float* mred = (float*)(sb + A_MRED);
    float* lred = (float*)(sb + A_LRED);

    // ldmatrix lane offsets (halves)
    const uint32_t aK = (uint32_t)(((((lane >> 3) & 1) << 3) + (lane & 7)) * SAK
                                   + (((lane >> 4) & 1) << 3));
    const uint32_t bK = (uint32_t)(((((lane >> 4) & 1) << 3) + (lane & 7)) * SAK
                                   + (((lane >> 3) & 1) << 3));
    const uint32_t aP = (uint32_t)(((((lane >> 3) & 1) << 3) + (lane & 7)) * SAP
                                   + (((lane >> 4) & 1) << 3));
    const uint32_t bV = (uint32_t)(((((lane >> 4) & 1) << 3) + (lane & 7)) * SAV
                                   + (((lane >> 3) & 1) << 3));

    int stg = 0;

#pragma unroll 1
    for (int ph = 0; ph < 2; ph++) {
        const int qt = ph ? (63 - p) : p;
        const int q0 = qt * 64;
        const int n  = qt + 1;

#pragma unroll
        for (int i = 0; i < 8; i++) {
            int c = tid + i * 256;
            int arr = c >> 10, idx = c & 1023;
            int r = idx >> 4, c8 = (idx & 15) * 8;
            const __nv_bfloat16* src = (arr ? g_Qlo : g_Qhi)
                + ((size_t)(b * T_ + q0 + r)) * HD_ + c8;
            *(uint4*)&sb[(arr ? AQ_LO : AQ_HI) + r * SAK + c8] = *(const uint4*)src;
        }
        load_kv_tile(b, 0, stg, tid, sbu);
        int cur = stg; stg ^= 1;
        __syncthreads();

        uint32_t qa_hi[8][4];
#pragma unroll
        for (int ks = 0; ks < 8; ks++)
            ldsm_x4(qa_hi[ks][0], qa_hi[ks][1], qa_hi[ks][2], qa_hi[ks][3],
                    sbu + 2 * (uint32_t)(AQ_HI + wm * 16 * SAK + ks * 16 + aK));

        float m0r = -INFINITY, m1r = -INFINITY, l0r = 0.f, l1r = 0.f;
        float oacc[8][4];
#pragma unroll
        for (int nf = 0; nf < 8; nf++)
#pragma unroll
            for (int c = 0; c < 4; c++) oacc[nf][c] = 0.f;

        const int row0 = wm * 16 + g;

#pragma unroll 1
        for (int kt = 0; kt < n; kt++) {
            if (kt + 1 < n) {
                load_kv_tile(b, kt + 1, stg, tid, sbu);
                stg ^= 1;
                asm volatile("cp.async.wait_group 1;" ::: "memory");
            } else {
                asm volatile("cp.async.wait_group 0;" ::: "memory");
            }
            __syncthreads();

            const uint32_t KhO = (uint32_t)(A_KOFF + cur * A_KSTG);

            float sacc[4][4];
#pragma unroll
            for (int nf = 0; nf < 4; nf++)
#pragma unroll
                for (int c = 0; c < 4; c++) sacc[nf][c] = 0.f;

#pragma unroll
            for (int pp = 0; pp < 2; pp++) {
                const uint32_t Kp = KhO + (uint32_t)(pp * 64 * SAK);
#pragma unroll
                for (int ks = 0; ks < 8; ks++) {
#pragma unroll
                    for (int n2 = 0; n2 < 2; n2++) {
                        uint32_t b0, b1, b2, b3;
                        ldsm_x4(b0, b1, b2, b3,
                                sbu + 2 * (Kp + (uint32_t)((wn * 32 + n2 * 16) * SAK
                                                           + ks * 16) + bK));
                        hmma16816(sacc[n2 * 2],     qa_hi[ks], b0, b1);
                        hmma16816(sacc[n2 * 2 + 1], qa_hi[ks], b2, b3);
                    }
                }
            }
#pragma unroll
            for (int ks = 0; ks < 8; ks++) {
                uint32_t a[4];
                ldsm_x4(a[0], a[1], a[2], a[3],
                        sbu + 2 * (uint32_t)(AQ_LO + wm * 16 * SAK + ks * 16 + aK));
#pragma unroll
                for (int n2 = 0; n2 < 2; n2++) {
                    uint32_t b0, b1, b2, b3;
                    ldsm_x4(b0, b1, b2, b3,
                            sbu + 2 * (KhO + (uint32_t)((wn * 32 + n2 * 16) * SAK
                                                        + ks * 16) + bK));
                    hmma16816(sacc[n2 * 2],     a, b0, b1);
                    hmma16816(sacc[n2 * 2 + 1], a, b2, b3);
                }
            }

            if (kt == qt) {
                const int gr = q0 + row0;
#pragma unroll
                for (int nf = 0; nf < 4; nf++) {
                    int col = kt * 64 + wn * 32 + nf * 8 + t * 2;
                    if (col     > gr)     sacc[nf][0] = -INFINITY;
                    if (col + 1 > gr)     sacc[nf][1] = -INFINITY;
                    if (col     > gr + 8) sacc[nf][2] = -INFINITY;
                    if (col + 1 > gr + 8) sacc[nf][3] = -INFINITY;
                }
            }

            float mx0 = -INFINITY, mx1 = -INFINITY;
#pragma unroll
            for (int nf = 0; nf < 4; nf++) {
                mx0 = fmaxf(mx0, fmaxf(sacc[nf][0], sacc[nf][1]));
                mx1 = fmaxf(mx1, fmaxf(sacc[nf][2], sacc[nf][3]));
            }
            mx0 = fmaxf(mx0, __shfl_xor_sync(0xffffffffu, mx0, 1));
            mx0 = fmaxf(mx0, __shfl_xor_sync(0xffffffffu, mx0, 2));
            mx1 = fmaxf(mx1, __shfl_xor_sync(0xffffffffu, mx1, 1));
            mx1 = fmaxf(mx1, __shfl_xor_sync(0xffffffffu, mx1, 2));
            if (t == 0) {
                mred[wn * 64 + row0]     = mx0;
                mred[wn * 64 + row0 + 8] = mx1;
            }
            __syncthreads();
            float mn0 = fmaxf(m0r, fmaxf(mx0, mred[(wn ^ 1) * 64 + row0]));
            float mn1 = fmaxf(m1r, fmaxf(mx1, mred[(wn ^ 1) * 64 + row0 + 8]));
            float al0 = __expf(m0r - mn0), al1 = __expf(m1r - mn1);
            m0r = mn0; m1r = mn1;

            float s0 = 0.f, s1 = 0.f;
#pragma unroll
            for (int nf = 0; nf < 4; nf++) {
                float p00 = __expf(sacc[nf][0] - mn0);
                float p01 = __expf(sacc[nf][1] - mn0);
                float p10 = __expf(sacc[nf][2] - mn1);
                float p11 = __expf(sacc[nf][3] - mn1);
                s0 += p00 + p01;
                s1 += p10 + p11;
                uint32_t h0, l0, h1, l1;
                split2(p00, p01, h0, l0);
                split2(p10, p11, h1, l1);
                int colh = wn * 32 + nf * 8 + t * 2;
                *(uint32_t*)&sb[A_PH + (row0)     * SAP + colh] = h0;
                *(uint32_t*)&sb[A_PL + (row0)     * SAP + colh] = l0;
                *(uint32_t*)&sb[A_PH + (row0 + 8) * SAP + colh] = h1;
                *(uint32_t*)&sb[A_PL + (row0 + 8) * SAP + colh] = l1;
            }
            s0 += __shfl_xor_sync(0xffffffffu, s0, 1);
            s0 += __shfl_xor_sync(0xffffffffu, s0, 2);
            s1 += __shfl_xor_sync(0xffffffffu, s1, 1);
            s1 += __shfl_xor_sync(0xffffffffu, s1, 2);
            if (t == 0) {
                lred[wn * 64 + row0]     = s0;
                lred[wn * 64 + row0 + 8] = s1;
            }
            __syncthreads();
            l0r = l0r * al0 + s0 + lred[(wn ^ 1) * 64 + row0];
            l1r = l1r * al1 + s1 + lred[(wn ^ 1) * 64 + row0 + 8];

#pragma unroll
            for (int nf = 0; nf < 8; nf++) {
                oacc[nf][0] *= al0; oacc[nf][1] *= al0;
                oacc[nf][2] *= al1; oacc[nf][3] *= al1;
            }

#pragma unroll
            for (int pass = 0; pass < 3; pass++) {
                const uint32_t ApO = (pass == 2) ? (uint32_t)A_PL : (uint32_t)A_PH;
                const uint32_t VpO = (uint32_t)(A_VOFF + cur * A_VSTG
                                                + ((pass == 1) ? A_VHALF : 0));
#pragma unroll
                for (int kk = 0; kk < 4; kk++) {
                    uint32_t a[4];
                    ldsm_x4(a[0], a[1], a[2], a[3],
                            sbu + 2 * (ApO + (uint32_t)(wm * 16 * SAP + kk * 16) + aP));
#pragma unroll
                    for (int n2 = 0; n2 < 4; n2++) {
                        uint32_t b0, b1, b2, b3;
                        ldsm_x4(b0, b1, b2, b3,
                                sbu + 2 * (VpO + (uint32_t)((wn * 64 + n2 * 16) * SAV
                                                            + kk * 16) + bV));
                        hmma16816(oacc[n2 * 2],     a, b0, b1);
                        hmma16816(oacc[n2 * 2 + 1], a, b2, b3);
                    }
                }
            }
            cur ^= (kt + 1 < n) ? 1 : 0;
            __syncthreads();
        }

        const float i0 = 1.0f / l0r, i1 = 1.0f / l1r;
        const int grow = b * T_ + q0 + row0;
#pragma unroll
        for (int nf = 0; nf < 8; nf++) {
            int col = wn * 64 + nf * 8 + t * 2;
            *(float2*)&out[(size_t)grow * HD_ + col] =
                make_float2(oacc[nf][0] * i0, oacc[nf][1] * i0);
            *(float2*)&out[(size_t)(grow + 8) * HD_ + col] =
                make_float2(oacc[nf][2] * i1, oacc[nf][3] * i1);
        }
    }
}

// ---------------------------------------------------------------------------
extern "C" void kernel_launch(void* const* d_in, const int* in_sizes, int n_in,
                              void* d_out, int out_size)
{
    const float* x  = (const float*)d_in[0];
    const float* Wq = (const float*)d_in[1];
    const float* Wk = (const float*)d_in[2];
    const float* Wv = (const float*)d_in[3];
    float* out = (float*)d_out;
    (void)in_sizes; (void)n_in; (void)out_size;

    cudaFuncSetAttribute(qkv_hmma_kernel,
                         cudaFuncAttributeMaxDynamicSharedMemorySize, QKV_SMEM_B);
    cudaFuncSetAttribute(attn_hmma_kernel,
                         cudaFuncAttributeMaxDynamicSharedMemorySize, ATTN_SMEM_B);

    convert_w_kernel<<<(3 * NE_ * HD_) / 256, 256>>>(Wq, Wk, Wv);
    qkv_hmma_kernel<<<dim3(2, 128), 256, QKV_SMEM_B>>>(x);
    attn_hmma_kernel<<<dim3(32, B_), 256, ATTN_SMEM_B>>>(out);
}